// round 1
// baseline (speedup 1.0000x reference)
#include <cuda_runtime.h>
#include <math.h>

#define N_NODES 10000
#define N_EDGES 320000
#define HID 128
#define NC0 10
#define NC1 5

// ---------------- device scratch (no runtime allocation allowed) ----------------
__device__ float g_deg[N_NODES];            // degree, then dinv in-place
__device__ int   g_cnt[N_NODES];
__device__ int   g_cur[N_NODES];
__device__ int   g_offs[N_NODES + 1];
__device__ int   g_perm[N_EDGES];
__device__ float g_hlin[N_NODES * HID];
__device__ float g_pre[N_NODES * HID];
__device__ float g_h1[N_NODES * HID];
__device__ float g_h2[N_NODES * HID];
__device__ float g_cat[N_NODES * 3 * HID];
__device__ float g_e1[N_NODES * HID];
__device__ float g_bottom[N_NODES * HID];
__device__ float g_rep[N_NODES * 3 * HID];
__device__ float g_f1[N_NODES * 512];
__device__ float g_stats1[2 * HID];
__device__ float g_stats2[2 * HID];
__device__ float g_bnscale[HID];
__device__ float g_bnshift[HID];
__device__ int   g_c0[N_NODES];
__device__ int   g_c1[NC0];
__device__ float g_xp0[NC0 * HID];
__device__ float g_A0[NC0 * NC0];
__device__ float g_latent0[NC0 * HID];
__device__ float g_latent1[NC1 * HID];

// ---------------- utility kernels ----------------
__global__ void k_zero() {
    int i = blockIdx.x * blockDim.x + threadIdx.x;
    if (i < N_NODES) { g_deg[i] = 0.f; g_cnt[i] = 0; g_cur[i] = 0; }
    if (i < 2 * HID) { g_stats1[i] = 0.f; g_stats2[i] = 0.f; }
    if (i < NC0 * HID) g_xp0[i] = 0.f;
    if (i < NC0 * NC0) g_A0[i] = 0.f;
}

__global__ void k_count(const int* __restrict__ col, const float* __restrict__ ew) {
    int e = blockIdx.x * blockDim.x + threadIdx.x;
    if (e >= N_EDGES) return;
    int c = col[e];
    atomicAdd(&g_cnt[c], 1);
    atomicAdd(&g_deg[c], ew[e]);
}

__global__ void k_scan() {   // exclusive scan of g_cnt[10000] -> g_offs, single block 1024
    __shared__ int sh[1024];
    const int PER = 10;
    int t = threadIdx.x;
    int base = t * PER;
    int loc[PER];
    int s = 0;
    #pragma unroll
    for (int p = 0; p < PER; p++) {
        int idx = base + p;
        int v = (idx < N_NODES) ? g_cnt[idx] : 0;
        loc[p] = s; s += v;
    }
    sh[t] = s; __syncthreads();
    for (int off = 1; off < 1024; off <<= 1) {
        int v = (t >= off) ? sh[t - off] : 0;
        __syncthreads();
        sh[t] += v;
        __syncthreads();
    }
    int excl = (t == 0) ? 0 : sh[t - 1];
    #pragma unroll
    for (int p = 0; p < PER; p++) {
        int idx = base + p;
        if (idx < N_NODES) g_offs[idx] = excl + loc[p];
    }
    if (t == 1023) g_offs[N_NODES] = sh[1023];
}

__global__ void k_fill(const int* __restrict__ col) {
    int e = blockIdx.x * blockDim.x + threadIdx.x;
    if (e >= N_EDGES) return;
    int c = col[e];
    int p = atomicAdd(&g_cur[c], 1);
    g_perm[g_offs[c] + p] = e;
}

__global__ void k_dinv() {
    int i = blockIdx.x * blockDim.x + threadIdx.x;
    if (i < N_NODES) g_deg[i] = rsqrtf(g_deg[i] + 1.0f);
}

// ---------------- SGEMM: C = act(A[MxK] @ B[KxN] + bias), 128x128 tile ----------------
__global__ __launch_bounds__(256) void sgemm(
    const float* __restrict__ A, const float* __restrict__ B,
    const float* __restrict__ bias, float* __restrict__ C,
    int M, int K, int Ncols, int doRelu)
{
    __shared__ float As[8][128];
    __shared__ float Bs[8][128];
    int m0 = blockIdx.x * 128, n0 = blockIdx.y * 128;
    int t = threadIdx.x;
    int tx = t & 15, ty = t >> 4;
    int aRow = t >> 1, aK = (t & 1) * 4;
    int bRow = t >> 5, bCol = (t & 31) * 4;
    float acc[8][8];
    #pragma unroll
    for (int i = 0; i < 8; i++)
        #pragma unroll
        for (int j = 0; j < 8; j++) acc[i][j] = 0.f;

    for (int k0 = 0; k0 < K; k0 += 8) {
        float4 av = make_float4(0.f, 0.f, 0.f, 0.f);
        if (m0 + aRow < M)
            av = *(const float4*)(A + (size_t)(m0 + aRow) * K + k0 + aK);
        As[aK + 0][aRow] = av.x; As[aK + 1][aRow] = av.y;
        As[aK + 2][aRow] = av.z; As[aK + 3][aRow] = av.w;
        *(float4*)&Bs[bRow][bCol] =
            *(const float4*)(B + (size_t)(k0 + bRow) * Ncols + n0 + bCol);
        __syncthreads();
        #pragma unroll
        for (int kk = 0; kk < 8; kk++) {
            float a[8], bb[8];
            #pragma unroll
            for (int i = 0; i < 8; i++) a[i] = As[kk][ty * 8 + i];
            #pragma unroll
            for (int j = 0; j < 8; j++) bb[j] = Bs[kk][tx * 8 + j];
            #pragma unroll
            for (int i = 0; i < 8; i++)
                #pragma unroll
                for (int j = 0; j < 8; j++) acc[i][j] += a[i] * bb[j];
        }
        __syncthreads();
    }
    #pragma unroll
    for (int i = 0; i < 8; i++) {
        int gm = m0 + ty * 8 + i;
        if (gm >= M) continue;
        #pragma unroll
        for (int j = 0; j < 8; j++) {
            int gn = n0 + tx * 8 + j;
            float v = acc[i][j];
            if (bias) v += bias[gn];
            if (doRelu) v = fmaxf(v, 0.f);
            C[(size_t)gm * Ncols + gn] = v;
        }
    }
}

// ---------------- GCN aggregation: warp per destination node ----------------
__global__ void k_gcn(const float* __restrict__ hlin, const float* __restrict__ bias,
                      const int* __restrict__ row, const float* __restrict__ ew)
{
    int warp = threadIdx.x >> 5, lane = threadIdx.x & 31;
    int i = blockIdx.x * 8 + warp;
    if (i >= N_NODES) return;
    float di = g_deg[i];  // dinv
    int s = g_offs[i], epnd = g_offs[i + 1];
    float4 acc = make_float4(0.f, 0.f, 0.f, 0.f);
    for (int idx = s; idx < epnd; idx++) {
        int e = g_perm[idx];
        int r = row[e];
        float nrm = g_deg[r] * ew[e] * di;
        float4 v = *(const float4*)(hlin + (size_t)r * HID + lane * 4);
        acc.x += nrm * v.x; acc.y += nrm * v.y;
        acc.z += nrm * v.z; acc.w += nrm * v.w;
    }
    float4 hs = *(const float4*)(hlin + (size_t)i * HID + lane * 4);
    float sl = di * di;
    float4 b4 = *(const float4*)(bias + lane * 4);
    float4 o;
    o.x = fmaxf(acc.x + hs.x * sl + b4.x, 0.f);
    o.y = fmaxf(acc.y + hs.y * sl + b4.y, 0.f);
    o.z = fmaxf(acc.z + hs.z * sl + b4.z, 0.f);
    o.w = fmaxf(acc.w + hs.w * sl + b4.w, 0.f);
    *(float4*)(g_pre + (size_t)i * HID + lane * 4) = o;
}

// ---------------- BatchNorm ----------------
__global__ void k_colstats(const float* __restrict__ src, float* __restrict__ stats) {
    int j = threadIdx.x;  // 128
    float s = 0.f, q = 0.f;
    for (int n = blockIdx.x; n < N_NODES; n += gridDim.x) {
        float v = src[(size_t)n * HID + j];
        s += v; q += v * v;
    }
    atomicAdd(&stats[j], s);
    atomicAdd(&stats[HID + j], q);
}

__global__ void k_bnfinal(const float* __restrict__ stats,
                          const float* __restrict__ g, const float* __restrict__ b) {
    int j = threadIdx.x;
    float m = stats[j] / (float)N_NODES;
    float var = stats[HID + j] / (float)N_NODES - m * m;
    float sc = g[j] * rsqrtf(var + 1e-5f);
    g_bnscale[j] = sc;
    g_bnshift[j] = b[j] - m * sc;
}

__global__ void k_bnapply(const float* __restrict__ src, float* __restrict__ dst) {
    int i = blockIdx.x * blockDim.x + threadIdx.x;
    if (i < N_NODES * HID) {
        int j = i & (HID - 1);
        dst[i] = src[i] * g_bnscale[j] + g_bnshift[j];
    }
}

// ---------------- concat builders ----------------
__global__ void k_buildcat(const float* __restrict__ x) {
    int n = blockIdx.x, t = threadIdx.x;
    g_cat[(size_t)n * 384 + t]       = x[(size_t)n * HID + t];
    g_cat[(size_t)n * 384 + 128 + t] = g_h1[(size_t)n * HID + t];
    g_cat[(size_t)n * 384 + 256 + t] = g_h2[(size_t)n * HID + t];
}

__global__ void k_buildrep() {
    int n = blockIdx.x, t = threadIdx.x;
    int c0 = g_c0[n];
    int c1 = g_c1[c0];
    g_rep[(size_t)n * 384 + t]       = g_bottom[(size_t)n * HID + t];
    g_rep[(size_t)n * 384 + 128 + t] = g_latent0[c0 * HID + t];
    g_rep[(size_t)n * 384 + 256 + t] = g_latent1[c1 * HID + t];
}

// ---------------- level-0 assignment (hard gumbel argmax) ----------------
__global__ void k_assign0(const float* __restrict__ w, const float* __restrict__ bias,
                          const float* __restrict__ gum) {
    __shared__ float sW[NC0][HID];  // transposed ml0_w
    int t = threadIdx.x;
    for (int i = t; i < HID * NC0; i += 256) {
        int k = i / NC0, c = i % NC0;
        sW[c][k] = w[i];
    }
    __syncthreads();
    int warp = t >> 5, lane = t & 31;
    int n = blockIdx.x * 8 + warp;
    if (n >= N_NODES) return;
    float4 xv = *(const float4*)(g_bottom + (size_t)n * HID + lane * 4);
    float best = -1e30f; int bi = 0;
    #pragma unroll
    for (int c = 0; c < NC0; c++) {
        float4 wv = *(float4*)&sW[c][lane * 4];
        float p = xv.x * wv.x + xv.y * wv.y + xv.z * wv.z + xv.w * wv.w;
        #pragma unroll
        for (int off = 16; off > 0; off >>= 1)
            p += __shfl_xor_sync(0xffffffffu, p, off);
        p += bias[c] + gum[(size_t)n * NC0 + c];
        if (p > best) { best = p; bi = c; }
    }
    if (lane == 0) g_c0[n] = bi;
}

// xp0[c] = sum of bottom rows in cluster c (sliced, atomics across slices)
__global__ void k_xp0() {
    int c = blockIdx.x % NC0;
    int slice = blockIdx.x / NC0;    // 8 slices
    int t = threadIdx.x;             // 128
    const int per = (N_NODES + 7) / 8;
    int n0 = slice * per;
    int n1 = n0 + per; if (n1 > N_NODES) n1 = N_NODES;
    float acc = 0.f;
    for (int n = n0; n < n1; n++) {
        if (g_c0[n] == c) acc += g_bottom[(size_t)n * HID + t];
    }
    atomicAdd(&g_xp0[c * HID + t], acc);
}

__global__ void k_A0(const int* __restrict__ row, const int* __restrict__ col,
                     const float* __restrict__ ew) {
    __shared__ float sA[NC0 * NC0];
    int t = threadIdx.x;
    if (t < NC0 * NC0) sA[t] = 0.f;
    __syncthreads();
    for (int e = blockIdx.x * blockDim.x + t; e < N_EDGES; e += gridDim.x * blockDim.x)
        atomicAdd(&sA[g_c0[row[e]] * NC0 + g_c0[col[e]]], ew[e]);
    __syncthreads();
    if (t < NC0 * NC0) atomicAdd(&g_A0[t], sA[t]);
}

// ---------------- tiny hierarchical pooling math, single block of 128 ----------------
__device__ __forceinline__ float blockReduce128(float v, float* red) {
    int t = threadIdx.x;
    red[t] = v; __syncthreads();
    #pragma unroll
    for (int off = 64; off > 0; off >>= 1) {
        if (t < off) red[t] += red[t + off];
        __syncthreads();
    }
    float r = red[0]; __syncthreads();
    return r;
}

__global__ void k_levels(const float* __restrict__ me0_w, const float* __restrict__ me0_b,
                         const float* __restrict__ ml1_w, const float* __restrict__ ml1_b,
                         const float* __restrict__ gum1,
                         const float* __restrict__ me1_w, const float* __restrict__ me1_b)
{
    __shared__ float sA0[NC0 * NC0];
    __shared__ float sXp[NC0][HID];
    __shared__ float sM[NC0][HID];
    __shared__ float sL0[NC0][HID];
    __shared__ float sXp1[NC1][HID];
    __shared__ float sM1[NC1][HID];
    __shared__ float red[HID];
    __shared__ float sZ[NC0][NC1];
    __shared__ float sA1[NC1 * NC1];
    __shared__ int   sC1[NC0];
    int t = threadIdx.x;

    // normalize A0 by total edge weight
    float a = (t < NC0 * NC0) ? g_A0[t] : 0.f;
    float S0 = blockReduce128(a, red);
    if (t < NC0 * NC0) sA0[t] = a / S0;
    __syncthreads();

    // l2-normalize xp0 rows
    for (int c = 0; c < NC0; c++) {
        float v = g_xp0[c * HID + t];
        float nsq = blockReduce128(v * v, red);
        float nrm = sqrtf(nsq);
        sXp[c][t] = v / fmaxf(nrm, 1e-12f);
    }
    __syncthreads();

    // M = A0n @ xp0
    for (int c = 0; c < NC0; c++) {
        float s = 0.f;
        #pragma unroll
        for (int k = 0; k < NC0; k++) s += sA0[c * NC0 + k] * sXp[k][t];
        sM[c][t] = s;
    }
    __syncthreads();

    // latent0 = tanh(M @ me0_w + me0_b)
    {
        float acc[NC0];
        #pragma unroll
        for (int c = 0; c < NC0; c++) acc[c] = me0_b[t];
        for (int k = 0; k < HID; k++) {
            float w = me0_w[k * HID + t];
            #pragma unroll
            for (int c = 0; c < NC0; c++) acc[c] += sM[c][k] * w;
        }
        #pragma unroll
        for (int c = 0; c < NC0; c++) {
            float v = tanhf(acc[c]);
            sL0[c][t] = v;
            g_latent0[c * HID + t] = v;
        }
    }
    __syncthreads();

    // logits1 + argmax -> c1
    if (t < NC0 * NC1) {
        int k = t / NC1, c = t % NC1;
        float s = ml1_b[c] + gum1[k * NC1 + c];
        for (int j = 0; j < HID; j++) s += sL0[k][j] * ml1_w[j * NC1 + c];
        sZ[k][c] = s;
    }
    __syncthreads();
    if (t < NC0) {
        float best = sZ[t][0]; int bi = 0;
        #pragma unroll
        for (int c = 1; c < NC1; c++)
            if (sZ[t][c] > best) { best = sZ[t][c]; bi = c; }
        sC1[t] = bi;
        g_c1[t] = bi;
    }
    __syncthreads();

    // xp1 rows (segment sum of latent0 over c1) + l2 normalize
    for (int c = 0; c < NC1; c++) {
        float v = 0.f;
        #pragma unroll
        for (int k = 0; k < NC0; k++)
            if (sC1[k] == c) v += sL0[k][t];
        float nsq = blockReduce128(v * v, red);
        float nrm = sqrtf(nsq);
        sXp1[c][t] = v / fmaxf(nrm, 1e-12f);
    }
    __syncthreads();

    // A1 = S^T A0n S, then normalize
    if (t < NC1 * NC1) {
        int aa = t / NC1, bb = t % NC1;
        float s = 0.f;
        for (int k = 0; k < NC0; k++)
            for (int l = 0; l < NC0; l++)
                if (sC1[k] == aa && sC1[l] == bb) s += sA0[k * NC0 + l];
        sA1[t] = s;
    }
    __syncthreads();
    float a1v = (t < NC1 * NC1) ? sA1[t] : 0.f;
    float S1 = blockReduce128(a1v, red);
    if (t < NC1 * NC1) sA1[t] = a1v / S1;
    __syncthreads();

    // M1 = A1n @ xp1 ; latent1 = tanh(M1 @ me1_w + me1_b)
    for (int c = 0; c < NC1; c++) {
        float s = 0.f;
        #pragma unroll
        for (int k = 0; k < NC1; k++) s += sA1[c * NC1 + k] * sXp1[k][t];
        sM1[c][t] = s;
    }
    __syncthreads();
    {
        float acc[NC1];
        #pragma unroll
        for (int c = 0; c < NC1; c++) acc[c] = me1_b[t];
        for (int k = 0; k < HID; k++) {
            float w = me1_w[k * HID + t];
            #pragma unroll
            for (int c = 0; c < NC1; c++) acc[c] += sM1[c][k] * w;
        }
        #pragma unroll
        for (int c = 0; c < NC1; c++) g_latent1[c * HID + t] = tanhf(acc[c]);
    }
}

// ---------------- final fc2 (K=512 -> 1) ----------------
__global__ void k_fc2(const float* __restrict__ w, const float* __restrict__ b,
                      float* __restrict__ out) {
    int warp = (blockIdx.x * blockDim.x + threadIdx.x) >> 5;
    int lane = threadIdx.x & 31;
    if (warp >= N_NODES) return;
    const float4* fp = (const float4*)(g_f1 + (size_t)warp * 512);
    const float4* wp = (const float4*)w;
    float s = 0.f;
    #pragma unroll
    for (int i = lane; i < 128; i += 32) {
        float4 aa = fp[i], cc = wp[i];
        s += aa.x * cc.x + aa.y * cc.y + aa.z * cc.z + aa.w * cc.w;
    }
    #pragma unroll
    for (int off = 16; off > 0; off >>= 1)
        s += __shfl_xor_sync(0xffffffffu, s, off);
    if (lane == 0) out[warp] = fmaxf(s + b[0], 0.f);
}

// ---------------- host ----------------
extern "C" void kernel_launch(void* const* d_in, const int* in_sizes, int n_in,
                              void* d_out, int out_size)
{
    const float* x       = (const float*)d_in[0];
    const float* ew      = (const float*)d_in[1];
    const float* gum0    = (const float*)d_in[2];
    const float* gum1    = (const float*)d_in[3];
    const float* conv1_w = (const float*)d_in[4];
    const float* conv1_b = (const float*)d_in[5];
    const float* conv2_w = (const float*)d_in[6];
    const float* conv2_b = (const float*)d_in[7];
    const float* bn1_g   = (const float*)d_in[8];
    const float* bn1_b   = (const float*)d_in[9];
    const float* bn2_g   = (const float*)d_in[10];
    const float* bn2_b   = (const float*)d_in[11];
    const float* enc1_w  = (const float*)d_in[12];
    const float* enc1_b  = (const float*)d_in[13];
    const float* enc2_w  = (const float*)d_in[14];
    const float* enc2_b  = (const float*)d_in[15];
    const float* ml0_w   = (const float*)d_in[16];
    const float* ml0_b   = (const float*)d_in[17];
    const float* ml1_w   = (const float*)d_in[18];
    const float* ml1_b   = (const float*)d_in[19];
    const float* me0_w   = (const float*)d_in[20];
    const float* me0_b   = (const float*)d_in[21];
    const float* me1_w   = (const float*)d_in[22];
    const float* me1_b   = (const float*)d_in[23];
    const float* fc1_w   = (const float*)d_in[24];
    const float* fc1_b   = (const float*)d_in[25];
    const float* fc2_w   = (const float*)d_in[26];
    const float* fc2_b   = (const float*)d_in[27];
    const int*   ei      = (const int*)d_in[28];
    const int* row = ei;
    const int* col = ei + N_EDGES;
    float* out = (float*)d_out;

    float *p_hlin, *p_pre, *p_h1, *p_h2, *p_cat, *p_e1, *p_bottom, *p_rep, *p_f1;
    float *p_stats1, *p_stats2;
    cudaGetSymbolAddress((void**)&p_hlin,   g_hlin);
    cudaGetSymbolAddress((void**)&p_pre,    g_pre);
    cudaGetSymbolAddress((void**)&p_h1,     g_h1);
    cudaGetSymbolAddress((void**)&p_h2,     g_h2);
    cudaGetSymbolAddress((void**)&p_cat,    g_cat);
    cudaGetSymbolAddress((void**)&p_e1,     g_e1);
    cudaGetSymbolAddress((void**)&p_bottom, g_bottom);
    cudaGetSymbolAddress((void**)&p_rep,    g_rep);
    cudaGetSymbolAddress((void**)&p_f1,     g_f1);
    cudaGetSymbolAddress((void**)&p_stats1, g_stats1);
    cudaGetSymbolAddress((void**)&p_stats2, g_stats2);

    dim3 gM1((N_NODES + 127) / 128, 1);
    dim3 gM4((N_NODES + 127) / 128, 4);

    k_zero<<<40, 256>>>();
    k_count<<<(N_EDGES + 255) / 256, 256>>>(col, ew);
    k_scan<<<1, 1024>>>();
    k_fill<<<(N_EDGES + 255) / 256, 256>>>(col);
    k_dinv<<<40, 256>>>();

    // conv1
    sgemm<<<gM1, 256>>>(x, conv1_w, nullptr, p_hlin, N_NODES, 128, 128, 0);
    k_gcn<<<1250, 256>>>(p_hlin, conv1_b, row, ew);
    k_colstats<<<256, 128>>>(p_pre, p_stats1);
    k_bnfinal<<<1, 128>>>(p_stats1, bn1_g, bn1_b);
    k_bnapply<<<(N_NODES * HID + 255) / 256, 256>>>(p_pre, p_h1);

    // conv2
    sgemm<<<gM1, 256>>>(p_h1, conv2_w, nullptr, p_hlin, N_NODES, 128, 128, 0);
    k_gcn<<<1250, 256>>>(p_hlin, conv2_b, row, ew);
    k_colstats<<<256, 128>>>(p_pre, p_stats2);
    k_bnfinal<<<1, 128>>>(p_stats2, bn2_g, bn2_b);
    k_bnapply<<<(N_NODES * HID + 255) / 256, 256>>>(p_pre, p_h2);

    // encoder
    k_buildcat<<<N_NODES, 128>>>(x);
    sgemm<<<gM1, 256>>>(p_cat, enc1_w, enc1_b, p_e1, N_NODES, 384, 128, 1);
    sgemm<<<gM1, 256>>>(p_e1, enc2_w, enc2_b, p_bottom, N_NODES, 128, 128, 1);

    // hierarchical pooling
    k_assign0<<<1250, 256>>>(ml0_w, ml0_b, gum0);
    k_xp0<<<80, 128>>>();
    k_A0<<<120, 256>>>(row, col, ew);
    k_levels<<<1, 128>>>(me0_w, me0_b, ml1_w, ml1_b, gum1, me1_w, me1_b);

    // head
    k_buildrep<<<N_NODES, 128>>>();
    sgemm<<<gM4, 256>>>(p_rep, fc1_w, fc1_b, p_f1, N_NODES, 384, 512, 1);
    k_fc2<<<1250, 256>>>(fc2_w, fc2_b, out);
}

// round 2
// speedup vs baseline: 1.5007x; 1.5007x over previous
#include <cuda_runtime.h>
#include <math.h>

#define N_NODES 10000
#define N_EDGES 320000
#define HID 128
#define NC0 10
#define NC1 5

// ---------------- device scratch ----------------
__device__ float g_deg[N_NODES];            // degree, then dinv in-place
__device__ int   g_cnt[N_NODES];
__device__ int   g_cur[N_NODES];
__device__ int   g_offs[N_NODES + 1];
__device__ int   g_perm[N_EDGES];
__device__ float g_hlin[N_NODES * HID];
__device__ float g_pre1[N_NODES * HID];
__device__ float g_pre2[N_NODES * HID];
__device__ float g_e1[N_NODES * HID];
__device__ float g_bottom[N_NODES * HID];
__device__ float g_f1[N_NODES * 512];
__device__ float g_stats1[2 * HID];
__device__ float g_stats2[2 * HID];
__device__ float g_sc1[HID];
__device__ float g_sh1[HID];
__device__ float g_sc2[HID];
__device__ float g_sh2[HID];
__device__ int   g_c0[N_NODES];
__device__ int   g_c1[NC0];
__device__ float g_xp0[NC0 * HID];
__device__ float g_A0[NC0 * NC0];
__device__ float g_latent0[NC0 * HID];
__device__ float g_latent1[NC1 * HID];

// ---------------- utility kernels ----------------
__global__ void k_zero() {
    int i = blockIdx.x * blockDim.x + threadIdx.x;
    if (i < N_NODES) { g_deg[i] = 0.f; g_cnt[i] = 0; g_cur[i] = 0; }
    if (i < 2 * HID) { g_stats1[i] = 0.f; g_stats2[i] = 0.f; }
    if (i < NC0 * HID) g_xp0[i] = 0.f;
    if (i < NC0 * NC0) g_A0[i] = 0.f;
}

__global__ void k_count(const int* __restrict__ col, const float* __restrict__ ew) {
    int e = blockIdx.x * blockDim.x + threadIdx.x;
    if (e >= N_EDGES) return;
    int c = col[e];
    atomicAdd(&g_cnt[c], 1);
    atomicAdd(&g_deg[c], ew[e]);
}

__global__ void k_scan() {   // exclusive scan of g_cnt -> g_offs
    __shared__ int sh[1024];
    const int PER = 10;
    int t = threadIdx.x;
    int base = t * PER;
    int loc[PER];
    int s = 0;
    #pragma unroll
    for (int p = 0; p < PER; p++) {
        int idx = base + p;
        int v = (idx < N_NODES) ? g_cnt[idx] : 0;
        loc[p] = s; s += v;
    }
    sh[t] = s; __syncthreads();
    for (int off = 1; off < 1024; off <<= 1) {
        int v = (t >= off) ? sh[t - off] : 0;
        __syncthreads();
        sh[t] += v;
        __syncthreads();
    }
    int excl = (t == 0) ? 0 : sh[t - 1];
    #pragma unroll
    for (int p = 0; p < PER; p++) {
        int idx = base + p;
        if (idx < N_NODES) g_offs[idx] = excl + loc[p];
    }
    if (t == 1023) g_offs[N_NODES] = sh[1023];
}

__global__ void k_fill(const int* __restrict__ col) {
    int e = blockIdx.x * blockDim.x + threadIdx.x;
    if (e < N_NODES) g_deg[e] = rsqrtf(g_deg[e] + 1.0f);   // fold dinv here
    if (e >= N_EDGES) return;
    int c = col[e];
    int p = atomicAdd(&g_cur[c], 1);
    g_perm[g_offs[c] + p] = e;
}

// ---------------- generalized segmented SGEMM ----------------
// C[M,Ncols] = act( A @ B + bias ), A's K dim = 128*nseg, segment s read from
// As_ptr[s] row r_s (optionally cluster-indirected), optionally scale/shifted.
#define BM 64
#define BN 128
#define BK 16

__global__ __launch_bounds__(256, 2) void sgemm(
    const float* __restrict__ A0, const float* __restrict__ A1, const float* __restrict__ A2,
    const float* __restrict__ sc0, const float* __restrict__ sh0,
    const float* __restrict__ sc1, const float* __restrict__ sh1,
    const float* __restrict__ sc2, const float* __restrict__ sh2,
    const float* __restrict__ B, const float* __restrict__ bias,
    float* __restrict__ C,
    int M, int nseg, int Ncols, int doRelu, int idxmode)
{
    __shared__ float As[2][BK][BM + 4];
    __shared__ float Bs[2][BK][BN];
    int t = threadIdx.x;
    int m0 = blockIdx.x * BM, n0 = blockIdx.y * BN;
    int aRow = t >> 2, aK = (t & 3) * 4;
    int bRow = t >> 4, bCol = (t & 15) * 4;
    int tx = t & 15, ty = t >> 4;
    int gm = m0 + aRow;
    bool mOK = gm < M;
    int r0 = mOK ? gm : 0;
    int r1 = r0, r2 = r0;
    if (idxmode && mOK) { r1 = g_c0[gm]; r2 = g_c1[r1]; }
    const float* pA0 = A0 ? A0 + (size_t)r0 * 128 : nullptr;
    const float* pA1 = A1 ? A1 + (size_t)r1 * 128 : nullptr;
    const float* pA2 = A2 ? A2 + (size_t)r2 * 128 : nullptr;

    int nT = nseg * 8;
    float4 aReg, bReg0, bReg1;

    auto gload = [&](int tile) {
        int kk0 = tile * BK;
        int seg = kk0 >> 7;
        int kin = (kk0 & 127) + aK;
        const float* bp; const float* scp; const float* shp;
        if (seg == 0)      { bp = pA0; scp = sc0; shp = sh0; }
        else if (seg == 1) { bp = pA1; scp = sc1; shp = sh1; }
        else               { bp = pA2; scp = sc2; shp = sh2; }
        float4 v = mOK ? *(const float4*)(bp + kin) : make_float4(0.f, 0.f, 0.f, 0.f);
        if (scp) {
            float4 s = *(const float4*)(scp + kin);
            float4 h = *(const float4*)(shp + kin);
            v.x = v.x * s.x + h.x; v.y = v.y * s.y + h.y;
            v.z = v.z * s.z + h.z; v.w = v.w * s.w + h.w;
        }
        aReg = v;
        const float* bb = B + (size_t)(kk0 + bRow) * Ncols + n0 + bCol;
        bReg0 = *(const float4*)bb;
        bReg1 = *(const float4*)(bb + 64);
    };
    auto sts = [&](int buf) {
        As[buf][aK + 0][aRow] = aReg.x;
        As[buf][aK + 1][aRow] = aReg.y;
        As[buf][aK + 2][aRow] = aReg.z;
        As[buf][aK + 3][aRow] = aReg.w;
        *(float4*)&Bs[buf][bRow][bCol]      = bReg0;
        *(float4*)&Bs[buf][bRow][bCol + 64] = bReg1;
    };

    gload(0); sts(0); __syncthreads();

    float acc[4][8];
    #pragma unroll
    for (int i = 0; i < 4; i++)
        #pragma unroll
        for (int j = 0; j < 8; j++) acc[i][j] = 0.f;

    int cur = 0;
    for (int tile = 0; tile < nT; ++tile) {
        bool more = tile + 1 < nT;
        if (more) gload(tile + 1);
        #pragma unroll
        for (int kk = 0; kk < BK; kk++) {
            float4 av  = *(const float4*)&As[cur][kk][ty * 4];
            float4 b0v = *(const float4*)&Bs[cur][kk][tx * 4];
            float4 b1v = *(const float4*)&Bs[cur][kk][tx * 4 + 64];
            float a_[4] = {av.x, av.y, av.z, av.w};
            float b_[8] = {b0v.x, b0v.y, b0v.z, b0v.w, b1v.x, b1v.y, b1v.z, b1v.w};
            #pragma unroll
            for (int i = 0; i < 4; i++)
                #pragma unroll
                for (int j = 0; j < 8; j++) acc[i][j] += a_[i] * b_[j];
        }
        if (more) sts(cur ^ 1);
        __syncthreads();
        cur ^= 1;
    }

    float4 bs0 = make_float4(0.f, 0.f, 0.f, 0.f), bs1 = bs0;
    if (bias) {
        bs0 = *(const float4*)(bias + n0 + tx * 4);
        bs1 = *(const float4*)(bias + n0 + tx * 4 + 64);
    }
    #pragma unroll
    for (int i = 0; i < 4; i++) {
        int gr = m0 + ty * 4 + i;
        if (gr >= M) continue;
        float* crow = C + (size_t)gr * Ncols + n0;
        float4 o0, o1;
        o0.x = acc[i][0] + bs0.x; o0.y = acc[i][1] + bs0.y;
        o0.z = acc[i][2] + bs0.z; o0.w = acc[i][3] + bs0.w;
        o1.x = acc[i][4] + bs1.x; o1.y = acc[i][5] + bs1.y;
        o1.z = acc[i][6] + bs1.z; o1.w = acc[i][7] + bs1.w;
        if (doRelu) {
            o0.x = fmaxf(o0.x, 0.f); o0.y = fmaxf(o0.y, 0.f);
            o0.z = fmaxf(o0.z, 0.f); o0.w = fmaxf(o0.w, 0.f);
            o1.x = fmaxf(o1.x, 0.f); o1.y = fmaxf(o1.y, 0.f);
            o1.z = fmaxf(o1.z, 0.f); o1.w = fmaxf(o1.w, 0.f);
        }
        *(float4*)(crow + tx * 4)      = o0;
        *(float4*)(crow + tx * 4 + 64) = o1;
    }
}

// ---------------- GCN aggregation + fused BN column stats ----------------
__global__ void k_gcn(const float* __restrict__ hlin, const float* __restrict__ bias,
                      const int* __restrict__ row, const float* __restrict__ ew,
                      float* __restrict__ pre, float* __restrict__ stats)
{
    __shared__ float sS[HID], sQ[HID];
    int t = threadIdx.x;
    if (t < HID) { sS[t] = 0.f; sQ[t] = 0.f; }
    __syncthreads();
    int warp = t >> 5, lane = t & 31;
    int i = blockIdx.x * 8 + warp;
    if (i < N_NODES) {
        float di = g_deg[i];
        int s = g_offs[i], epnd = g_offs[i + 1];
        float4 acc = make_float4(0.f, 0.f, 0.f, 0.f);
        for (int idx = s; idx < epnd; idx++) {
            int e = g_perm[idx];
            int r = row[e];
            float nrm = g_deg[r] * ew[e] * di;
            float4 v = *(const float4*)(hlin + (size_t)r * HID + lane * 4);
            acc.x += nrm * v.x; acc.y += nrm * v.y;
            acc.z += nrm * v.z; acc.w += nrm * v.w;
        }
        float4 hs = *(const float4*)(hlin + (size_t)i * HID + lane * 4);
        float sl = di * di;
        float4 b4 = *(const float4*)(bias + lane * 4);
        float4 o;
        o.x = fmaxf(acc.x + hs.x * sl + b4.x, 0.f);
        o.y = fmaxf(acc.y + hs.y * sl + b4.y, 0.f);
        o.z = fmaxf(acc.z + hs.z * sl + b4.z, 0.f);
        o.w = fmaxf(acc.w + hs.w * sl + b4.w, 0.f);
        *(float4*)(pre + (size_t)i * HID + lane * 4) = o;
        int f = lane * 4;
        atomicAdd(&sS[f + 0], o.x); atomicAdd(&sQ[f + 0], o.x * o.x);
        atomicAdd(&sS[f + 1], o.y); atomicAdd(&sQ[f + 1], o.y * o.y);
        atomicAdd(&sS[f + 2], o.z); atomicAdd(&sQ[f + 2], o.z * o.z);
        atomicAdd(&sS[f + 3], o.w); atomicAdd(&sQ[f + 3], o.w * o.w);
    }
    __syncthreads();
    if (t < HID) {
        atomicAdd(&stats[t], sS[t]);
        atomicAdd(&stats[HID + t], sQ[t]);
    }
}

__global__ void k_bnfinal(const float* __restrict__ stats,
                          const float* __restrict__ g, const float* __restrict__ b,
                          float* __restrict__ scale, float* __restrict__ shift) {
    int j = threadIdx.x;
    float m = stats[j] / (float)N_NODES;
    float var = stats[HID + j] / (float)N_NODES - m * m;
    float sc = g[j] * rsqrtf(var + 1e-5f);
    scale[j] = sc;
    shift[j] = b[j] - m * sc;
}

// ---------------- level-0 assignment + fused xp0 ----------------
__global__ void k_assign0(const float* __restrict__ w, const float* __restrict__ bias,
                          const float* __restrict__ gum) {
    __shared__ float sW[NC0][HID];
    __shared__ float sAcc[NC0][HID];
    int t = threadIdx.x;
    for (int i = t; i < HID * NC0; i += 256) {
        int k = i / NC0, c = i % NC0;
        sW[c][k] = w[i];
        ((float*)sAcc)[i] = 0.f;
    }
    __syncthreads();
    int warp = t >> 5, lane = t & 31;
    for (int n = blockIdx.x * 8 + warp; n < N_NODES; n += gridDim.x * 8) {
        float4 xv = *(const float4*)(g_bottom + (size_t)n * HID + lane * 4);
        float best = -1e30f; int bi = 0;
        #pragma unroll
        for (int c = 0; c < NC0; c++) {
            float4 wv = *(float4*)&sW[c][lane * 4];
            float p = xv.x * wv.x + xv.y * wv.y + xv.z * wv.z + xv.w * wv.w;
            #pragma unroll
            for (int off = 16; off > 0; off >>= 1)
                p += __shfl_xor_sync(0xffffffffu, p, off);
            p += bias[c] + gum[(size_t)n * NC0 + c];
            if (p > best) { best = p; bi = c; }
        }
        if (lane == 0) g_c0[n] = bi;
        int f = lane * 4;
        atomicAdd(&sAcc[bi][f + 0], xv.x);
        atomicAdd(&sAcc[bi][f + 1], xv.y);
        atomicAdd(&sAcc[bi][f + 2], xv.z);
        atomicAdd(&sAcc[bi][f + 3], xv.w);
    }
    __syncthreads();
    for (int i = t; i < NC0 * HID; i += 256)
        atomicAdd(&g_xp0[i], ((float*)sAcc)[i]);
}

__global__ void k_A0(const int* __restrict__ row, const int* __restrict__ col,
                     const float* __restrict__ ew) {
    __shared__ float sA[NC0 * NC0];
    int t = threadIdx.x;
    if (t < NC0 * NC0) sA[t] = 0.f;
    __syncthreads();
    for (int e = blockIdx.x * blockDim.x + t; e < N_EDGES; e += gridDim.x * blockDim.x)
        atomicAdd(&sA[g_c0[row[e]] * NC0 + g_c0[col[e]]], ew[e]);
    __syncthreads();
    if (t < NC0 * NC0) atomicAdd(&g_A0[t], sA[t]);
}

// ---------------- tiny hierarchical pooling math ----------------
__device__ __forceinline__ float blockReduce128(float v, float* red) {
    int t = threadIdx.x;
    red[t] = v; __syncthreads();
    #pragma unroll
    for (int off = 64; off > 0; off >>= 1) {
        if (t < off) red[t] += red[t + off];
        __syncthreads();
    }
    float r = red[0]; __syncthreads();
    return r;
}

__global__ void k_levels(const float* __restrict__ me0_w, const float* __restrict__ me0_b,
                         const float* __restrict__ ml1_w, const float* __restrict__ ml1_b,
                         const float* __restrict__ gum1,
                         const float* __restrict__ me1_w, const float* __restrict__ me1_b)
{
    __shared__ float sA0[NC0 * NC0];
    __shared__ float sXp[NC0][HID];
    __shared__ float sM[NC0][HID];
    __shared__ float sL0[NC0][HID];
    __shared__ float sXp1[NC1][HID];
    __shared__ float sM1[NC1][HID];
    __shared__ float red[HID];
    __shared__ float sZ[NC0][NC1];
    __shared__ float sA1[NC1 * NC1];
    __shared__ int   sC1[NC0];
    int t = threadIdx.x;

    float a = (t < NC0 * NC0) ? g_A0[t] : 0.f;
    float S0 = blockReduce128(a, red);
    if (t < NC0 * NC0) sA0[t] = a / S0;
    __syncthreads();

    for (int c = 0; c < NC0; c++) {
        float v = g_xp0[c * HID + t];
        float nsq = blockReduce128(v * v, red);
        float nrm = sqrtf(nsq);
        sXp[c][t] = v / fmaxf(nrm, 1e-12f);
    }
    __syncthreads();

    for (int c = 0; c < NC0; c++) {
        float s = 0.f;
        #pragma unroll
        for (int k = 0; k < NC0; k++) s += sA0[c * NC0 + k] * sXp[k][t];
        sM[c][t] = s;
    }
    __syncthreads();

    {
        float acc[NC0];
        #pragma unroll
        for (int c = 0; c < NC0; c++) acc[c] = me0_b[t];
        for (int k = 0; k < HID; k++) {
            float w = me0_w[k * HID + t];
            #pragma unroll
            for (int c = 0; c < NC0; c++) acc[c] += sM[c][k] * w;
        }
        #pragma unroll
        for (int c = 0; c < NC0; c++) {
            float v = tanhf(acc[c]);
            sL0[c][t] = v;
            g_latent0[c * HID + t] = v;
        }
    }
    __syncthreads();

    if (t < NC0 * NC1) {
        int k = t / NC1, c = t % NC1;
        float s = ml1_b[c] + gum1[k * NC1 + c];
        for (int j = 0; j < HID; j++) s += sL0[k][j] * ml1_w[j * NC1 + c];
        sZ[k][c] = s;
    }
    __syncthreads();
    if (t < NC0) {
        float best = sZ[t][0]; int bi = 0;
        #pragma unroll
        for (int c = 1; c < NC1; c++)
            if (sZ[t][c] > best) { best = sZ[t][c]; bi = c; }
        sC1[t] = bi;
        g_c1[t] = bi;
    }
    __syncthreads();

    for (int c = 0; c < NC1; c++) {
        float v = 0.f;
        #pragma unroll
        for (int k = 0; k < NC0; k++)
            if (sC1[k] == c) v += sL0[k][t];
        float nsq = blockReduce128(v * v, red);
        float nrm = sqrtf(nsq);
        sXp1[c][t] = v / fmaxf(nrm, 1e-12f);
    }
    __syncthreads();

    if (t < NC1 * NC1) {
        int aa = t / NC1, bb = t % NC1;
        float s = 0.f;
        for (int k = 0; k < NC0; k++)
            for (int l = 0; l < NC0; l++)
                if (sC1[k] == aa && sC1[l] == bb) s += sA0[k * NC0 + l];
        sA1[t] = s;
    }
    __syncthreads();
    float a1v = (t < NC1 * NC1) ? sA1[t] : 0.f;
    float S1 = blockReduce128(a1v, red);
    if (t < NC1 * NC1) sA1[t] = a1v / S1;
    __syncthreads();

    for (int c = 0; c < NC1; c++) {
        float s = 0.f;
        #pragma unroll
        for (int k = 0; k < NC1; k++) s += sA1[c * NC1 + k] * sXp1[k][t];
        sM1[c][t] = s;
    }
    __syncthreads();
    {
        float acc[NC1];
        #pragma unroll
        for (int c = 0; c < NC1; c++) acc[c] = me1_b[t];
        for (int k = 0; k < HID; k++) {
            float w = me1_w[k * HID + t];
            #pragma unroll
            for (int c = 0; c < NC1; c++) acc[c] += sM1[c][k] * w;
        }
        #pragma unroll
        for (int c = 0; c < NC1; c++) g_latent1[c * HID + t] = tanhf(acc[c]);
    }
}

// ---------------- final fc2 ----------------
__global__ void k_fc2(const float* __restrict__ w, const float* __restrict__ b,
                      float* __restrict__ out) {
    int warp = (blockIdx.x * blockDim.x + threadIdx.x) >> 5;
    int lane = threadIdx.x & 31;
    if (warp >= N_NODES) return;
    const float4* fp = (const float4*)(g_f1 + (size_t)warp * 512);
    const float4* wp = (const float4*)w;
    float s = 0.f;
    #pragma unroll
    for (int i = lane; i < 128; i += 32) {
        float4 aa = fp[i], cc = wp[i];
        s += aa.x * cc.x + aa.y * cc.y + aa.z * cc.z + aa.w * cc.w;
    }
    #pragma unroll
    for (int off = 16; off > 0; off >>= 1)
        s += __shfl_xor_sync(0xffffffffu, s, off);
    if (lane == 0) out[warp] = fmaxf(s + b[0], 0.f);
}

// ---------------- host ----------------
extern "C" void kernel_launch(void* const* d_in, const int* in_sizes, int n_in,
                              void* d_out, int out_size)
{
    const float* x       = (const float*)d_in[0];
    const float* ew      = (const float*)d_in[1];
    const float* gum0    = (const float*)d_in[2];
    const float* gum1    = (const float*)d_in[3];
    const float* conv1_w = (const float*)d_in[4];
    const float* conv1_b = (const float*)d_in[5];
    const float* conv2_w = (const float*)d_in[6];
    const float* conv2_b = (const float*)d_in[7];
    const float* bn1_g   = (const float*)d_in[8];
    const float* bn1_b   = (const float*)d_in[9];
    const float* bn2_g   = (const float*)d_in[10];
    const float* bn2_b   = (const float*)d_in[11];
    const float* enc1_w  = (const float*)d_in[12];
    const float* enc1_b  = (const float*)d_in[13];
    const float* enc2_w  = (const float*)d_in[14];
    const float* enc2_b  = (const float*)d_in[15];
    const float* ml0_w   = (const float*)d_in[16];
    const float* ml0_b   = (const float*)d_in[17];
    const float* ml1_w   = (const float*)d_in[18];
    const float* ml1_b   = (const float*)d_in[19];
    const float* me0_w   = (const float*)d_in[20];
    const float* me0_b   = (const float*)d_in[21];
    const float* me1_w   = (const float*)d_in[22];
    const float* me1_b   = (const float*)d_in[23];
    const float* fc1_w   = (const float*)d_in[24];
    const float* fc1_b   = (const float*)d_in[25];
    const float* fc2_w   = (const float*)d_in[26];
    const float* fc2_b   = (const float*)d_in[27];
    const int*   ei      = (const int*)d_in[28];
    const int* row = ei;
    const int* col = ei + N_EDGES;
    float* out = (float*)d_out;

    float *p_hlin, *p_pre1, *p_pre2, *p_e1, *p_bottom, *p_f1;
    float *p_stats1, *p_stats2, *p_sc1, *p_sh1, *p_sc2, *p_sh2, *p_lat0, *p_lat1;
    cudaGetSymbolAddress((void**)&p_hlin,   g_hlin);
    cudaGetSymbolAddress((void**)&p_pre1,   g_pre1);
    cudaGetSymbolAddress((void**)&p_pre2,   g_pre2);
    cudaGetSymbolAddress((void**)&p_e1,     g_e1);
    cudaGetSymbolAddress((void**)&p_bottom, g_bottom);
    cudaGetSymbolAddress((void**)&p_f1,     g_f1);
    cudaGetSymbolAddress((void**)&p_stats1, g_stats1);
    cudaGetSymbolAddress((void**)&p_stats2, g_stats2);
    cudaGetSymbolAddress((void**)&p_sc1,    g_sc1);
    cudaGetSymbolAddress((void**)&p_sh1,    g_sh1);
    cudaGetSymbolAddress((void**)&p_sc2,    g_sc2);
    cudaGetSymbolAddress((void**)&p_sh2,    g_sh2);
    cudaGetSymbolAddress((void**)&p_lat0,   g_latent0);
    cudaGetSymbolAddress((void**)&p_lat1,   g_latent1);

    const int MB = (N_NODES + BM - 1) / BM;   // 157
    dim3 g1(MB, 1), g4(MB, 4);

    k_zero<<<40, 256>>>();
    k_count<<<(N_EDGES + 255) / 256, 256>>>(col, ew);
    k_scan<<<1, 1024>>>();
    k_fill<<<(N_EDGES + 255) / 256, 256>>>(col);

    // conv1: hlin = x @ conv1_w
    sgemm<<<g1, 256>>>(x, nullptr, nullptr,
                       nullptr, nullptr, nullptr, nullptr, nullptr, nullptr,
                       conv1_w, nullptr, p_hlin, N_NODES, 1, 128, 0, 0);
    k_gcn<<<1250, 256>>>(p_hlin, conv1_b, row, ew, p_pre1, p_stats1);
    k_bnfinal<<<1, 128>>>(p_stats1, bn1_g, bn1_b, p_sc1, p_sh1);

    // conv2: hlin = bn1(pre1) @ conv2_w
    sgemm<<<g1, 256>>>(p_pre1, nullptr, nullptr,
                       p_sc1, p_sh1, nullptr, nullptr, nullptr, nullptr,
                       conv2_w, nullptr, p_hlin, N_NODES, 1, 128, 0, 0);
    k_gcn<<<1250, 256>>>(p_hlin, conv2_b, row, ew, p_pre2, p_stats2);
    k_bnfinal<<<1, 128>>>(p_stats2, bn2_g, bn2_b, p_sc2, p_sh2);

    // enc1: e1 = relu([x | bn1(pre1) | bn2(pre2)] @ enc1_w + b)
    sgemm<<<g1, 256>>>(x, p_pre1, p_pre2,
                       nullptr, nullptr, p_sc1, p_sh1, p_sc2, p_sh2,
                       enc1_w, enc1_b, p_e1, N_NODES, 3, 128, 1, 0);
    // enc2: bottom = relu(e1 @ enc2_w + b)
    sgemm<<<g1, 256>>>(p_e1, nullptr, nullptr,
                       nullptr, nullptr, nullptr, nullptr, nullptr, nullptr,
                       enc2_w, enc2_b, p_bottom, N_NODES, 1, 128, 1, 0);

    // hierarchical pooling
    k_assign0<<<80, 256>>>(ml0_w, ml0_b, gum0);
    k_A0<<<120, 256>>>(row, col, ew);
    k_levels<<<1, 128>>>(me0_w, me0_b, ml1_w, ml1_b, gum1, me1_w, me1_b);

    // fc1: f1 = relu([bottom | latent0[c0] | latent1[c1[c0]]] @ fc1_w + b)
    sgemm<<<g4, 256>>>(p_bottom, p_lat0, p_lat1,
                       nullptr, nullptr, nullptr, nullptr, nullptr, nullptr,
                       fc1_w, fc1_b, p_f1, N_NODES, 3, 512, 1, 1);
    k_fc2<<<1250, 256>>>(fc2_w, fc2_b, out);
}

// round 4
// speedup vs baseline: 1.9583x; 1.3049x over previous
#include <cuda_runtime.h>
#include <cuda_bf16.h>
#include <stdint.h>
#include <math.h>

#define N_NODES 10000
#define N_EDGES 320000
#define HID 128
#define NC0 10
#define NC1 5

// ---------------- device scratch ----------------
__device__ float g_deg[N_NODES];
__device__ int   g_cnt[N_NODES];
__device__ int   g_cur[N_NODES];
__device__ int   g_offs[N_NODES + 1];
__device__ int   g_perm[N_EDGES];
__device__ float g_hlin[N_NODES * HID];
__device__ float g_pre1[N_NODES * HID];
__device__ float g_pre2[N_NODES * HID];
__device__ float g_e1[N_NODES * HID];
__device__ float g_bottom[N_NODES * HID];
__device__ float g_f1[N_NODES * 512];
__device__ float g_stats1[2 * HID];
__device__ float g_stats2[2 * HID];
__device__ float g_sc1[HID];
__device__ float g_sh1[HID];
__device__ float g_sc2[HID];
__device__ float g_sh2[HID];
__device__ int   g_c0[N_NODES];
__device__ int   g_c1[NC0];
__device__ float g_xp0[NC0 * HID];
__device__ float g_A0[NC0 * NC0];
__device__ float g_latent0[NC0 * HID];
__device__ float g_latent1[NC1 * HID];

// pre-converted transposed weights [N][K] bf16 hi/lo
#define WO_CONV1 0
#define WO_CONV2 16384
#define WO_ENC1  32768
#define WO_ENC2  81920
#define WO_FC1   98304
#define W_TOTAL  294912
__device__ __align__(16) __nv_bfloat16 g_wh[W_TOTAL];
__device__ __align__(16) __nv_bfloat16 g_wl[W_TOTAL];

// ---------------- PTX wrappers (baseline ISA, compiles for compute_103) ----------------
__device__ __forceinline__ uint32_t smem_u32(const void* p) {
    uint32_t a;
    asm("{ .reg .u64 t; cvta.to.shared.u64 t, %1; cvt.u32.u64 %0, t; }" : "=r"(a) : "l"(p));
    return a;
}
__device__ __forceinline__ void ldsm4(uint32_t r[4], uint32_t addr) {
    asm volatile("ldmatrix.sync.aligned.m8n8.x4.shared.b16 {%0,%1,%2,%3}, [%4];"
        : "=r"(r[0]), "=r"(r[1]), "=r"(r[2]), "=r"(r[3]) : "r"(addr));
}
__device__ __forceinline__ void mma16816(float d[4], const uint32_t a[4], const uint32_t b[2]) {
    asm volatile("mma.sync.aligned.m16n8k16.row.col.f32.bf16.bf16.f32 "
        "{%0,%1,%2,%3}, {%4,%5,%6,%7}, {%8,%9}, {%0,%1,%2,%3};"
        : "+f"(d[0]), "+f"(d[1]), "+f"(d[2]), "+f"(d[3])
        : "r"(a[0]), "r"(a[1]), "r"(a[2]), "r"(a[3]), "r"(b[0]), "r"(b[1]));
}
// swizzled byte offset inside a [rows][32 bf16] tile (row stride 64B)
__device__ __forceinline__ uint32_t swz(int row, int kb) {
    int c = kb >> 4;
    int rem = kb & 15;
    int cp = c ^ ((row >> 1) & 3);
    return (uint32_t)(row * 64 + cp * 16 + rem);
}

// ---------------- weight prep: transpose + hi/lo split ----------------
__global__ void k_wprep(const float* __restrict__ w1, const float* __restrict__ w2,
                        const float* __restrict__ we1, const float* __restrict__ we2,
                        const float* __restrict__ wf1) {
    int i = blockIdx.x * blockDim.x + threadIdx.x;
    if (i >= W_TOTAL) return;
    const float* w; int K, Nn; int d = i;
    if (d < 16384)       { w = w1;  K = 128; Nn = 128; }
    else if (d < 32768)  { w = w2;  K = 128; Nn = 128; d -= 16384; }
    else if (d < 81920)  { w = we1; K = 384; Nn = 128; d -= 32768; }
    else if (d < 98304)  { w = we2; K = 128; Nn = 128; d -= 81920; }
    else                 { w = wf1; K = 384; Nn = 512; d -= 98304; }
    int n = d / K, k = d % K;
    float v = w[(size_t)k * Nn + n];
    __nv_bfloat16 h = __float2bfloat16(v);
    float l = v - __bfloat162float(h);
    g_wh[i] = h;
    g_wl[i] = __float2bfloat16(l);
}

// ---------------- bf16x3 tensor-core GEMM via mma.sync ----------------
// C[M,Ncols] = act(A @ B + bias); A's K = 128*nseg from up to 3 segments
// (optional scale/shift, optional cluster indirection). B is bf16 hi/lo [N][K].
__global__ __launch_bounds__(256, 1)
void tgemm(const float* __restrict__ A0, const float* __restrict__ A1, const float* __restrict__ A2,
           const float* __restrict__ sc0, const float* __restrict__ sh0,
           const float* __restrict__ sc1, const float* __restrict__ sh1,
           const float* __restrict__ sc2, const float* __restrict__ sh2,
           const __nv_bfloat16* __restrict__ Bh, const __nv_bfloat16* __restrict__ Bl,
           const float* __restrict__ bias, float* __restrict__ C,
           int M, int nseg, int Ncols, int doRelu, int idxmode)
{
    __shared__ __align__(16) char sAhi[8192];
    __shared__ __align__(16) char sAlo[8192];
    __shared__ __align__(16) char sBhi[8192];
    __shared__ __align__(16) char sBlo[8192];

    int t = threadIdx.x;
    int wid = t >> 5, lane = t & 31;
    int wm = wid >> 1, wn = wid & 1;           // 4 x 2 warp grid
    int m0 = blockIdx.x * 128, n0 = blockIdx.y * 128;

    // --- A row setup for staging (thread t stages row t>>1, half t&1) ---
    int sRow = t >> 1, sHalf = t & 1;
    int gm = m0 + sRow;
    bool mOK = gm < M;
    int gi = mOK ? gm : 0;
    int i1 = gi, i2 = gi;
    if (idxmode && mOK) { i1 = g_c0[gi]; i2 = g_c1[i1]; }
    const float* rp[3];
    rp[0] = A0 ? A0 + (size_t)gi * 128 : (const float*)0;
    rp[1] = A1 ? A1 + (size_t)i1 * 128 : (const float*)0;
    rp[2] = A2 ? A2 + (size_t)i2 * 128 : (const float*)0;
    const float* scp[3] = { sc0, sc1, sc2 };
    const float* shp[3] = { sh0, sh1, sh2 };

    int Kfull = nseg * 128;
    int nChunks = nseg * 4;                    // 32 K per chunk

    uint32_t uAhi = smem_u32(sAhi), uAlo = smem_u32(sAlo);
    uint32_t uBhi = smem_u32(sBhi), uBlo = smem_u32(sBlo);

    float d[2][8][4];
    #pragma unroll
    for (int a = 0; a < 2; a++)
        #pragma unroll
        for (int b = 0; b < 8; b++)
            #pragma unroll
            for (int c = 0; c < 4; c++) d[a][b][c] = 0.f;

    for (int ch = 0; ch < nChunks; ch++) {
        int koff = ch * 32;
        int seg = koff >> 7;
        int kin = (koff & 127) + sHalf * 16;

        // ---- stage A (16 floats -> bf16 hi/lo, swizzled) ----
        {
            const float* ap = rp[seg] + kin;
            const float* sp = scp[seg];
            const float* hp = shp[seg];
            uint32_t hi[8], lo[8];
            #pragma unroll
            for (int j = 0; j < 4; j++) {
                float4 v = mOK ? *(const float4*)(ap + j * 4) : make_float4(0.f, 0.f, 0.f, 0.f);
                if (sp) {
                    float4 s = *(const float4*)(sp + kin + j * 4);
                    float4 h = *(const float4*)(hp + kin + j * 4);
                    v.x = v.x * s.x + h.x; v.y = v.y * s.y + h.y;
                    v.z = v.z * s.z + h.z; v.w = v.w * s.w + h.w;
                }
                __nv_bfloat162 h01 = __floats2bfloat162_rn(v.x, v.y);
                __nv_bfloat162 h23 = __floats2bfloat162_rn(v.z, v.w);
                __nv_bfloat162 l01 = __floats2bfloat162_rn(v.x - __bfloat162float(h01.x),
                                                           v.y - __bfloat162float(h01.y));
                __nv_bfloat162 l23 = __floats2bfloat162_rn(v.z - __bfloat162float(h23.x),
                                                           v.w - __bfloat162float(h23.y));
                hi[j * 2 + 0] = *(uint32_t*)&h01; hi[j * 2 + 1] = *(uint32_t*)&h23;
                lo[j * 2 + 0] = *(uint32_t*)&l01; lo[j * 2 + 1] = *(uint32_t*)&l23;
            }
            #pragma unroll
            for (int c = 0; c < 2; c++) {
                uint32_t kb = (uint32_t)(sHalf * 32 + c * 16);
                uint32_t sw = swz(sRow, kb);
                *(uint4*)(sAhi + sw) = make_uint4(hi[c * 4], hi[c * 4 + 1], hi[c * 4 + 2], hi[c * 4 + 3]);
                *(uint4*)(sAlo + sw) = make_uint4(lo[c * 4], lo[c * 4 + 1], lo[c * 4 + 2], lo[c * 4 + 3]);
            }
        }
        // ---- stage B (16 bf16 from pre-converted hi/lo, swizzled) ----
        {
            int n = sRow;
            size_t gb = (size_t)(n0 + n) * Kfull + koff + sHalf * 16;
            uint4 vh0 = *(const uint4*)(Bh + gb);
            uint4 vh1 = *(const uint4*)(Bh + gb + 8);
            uint4 vl0 = *(const uint4*)(Bl + gb);
            uint4 vl1 = *(const uint4*)(Bl + gb + 8);
            uint32_t kb0 = (uint32_t)(sHalf * 32);
            uint32_t sw0 = swz(n, kb0), sw1 = swz(n, kb0 + 16);
            *(uint4*)(sBhi + sw0) = vh0;
            *(uint4*)(sBhi + sw1) = vh1;
            *(uint4*)(sBlo + sw0) = vl0;
            *(uint4*)(sBlo + sw1) = vl1;
        }
        __syncthreads();

        // ---- compute: two k16 steps ----
        int mid = lane >> 3, r8 = lane & 7;
        #pragma unroll
        for (int kk = 0; kk < 2; kk++) {
            uint32_t ah[2][4], al[2][4];
            #pragma unroll
            for (int mt = 0; mt < 2; mt++) {
                int row = wm * 32 + mt * 16 + (mid & 1) * 8 + r8;
                uint32_t kb = (uint32_t)(kk * 32 + (mid >> 1) * 16);
                uint32_t sw = swz(row, kb);
                ldsm4(ah[mt], uAhi + sw);
                ldsm4(al[mt], uAlo + sw);
            }
            uint32_t bh[8][2], bl[8][2];
            #pragma unroll
            for (int ntp = 0; ntp < 4; ntp++) {
                int row = wn * 64 + ntp * 16 + (mid >> 1) * 8 + r8;
                uint32_t kb = (uint32_t)(kk * 32 + (mid & 1) * 16);
                uint32_t sw = swz(row, kb);
                uint32_t tmp[4];
                ldsm4(tmp, uBhi + sw);
                bh[ntp * 2 + 0][0] = tmp[0]; bh[ntp * 2 + 0][1] = tmp[1];
                bh[ntp * 2 + 1][0] = tmp[2]; bh[ntp * 2 + 1][1] = tmp[3];
                ldsm4(tmp, uBlo + sw);
                bl[ntp * 2 + 0][0] = tmp[0]; bl[ntp * 2 + 0][1] = tmp[1];
                bl[ntp * 2 + 1][0] = tmp[2]; bl[ntp * 2 + 1][1] = tmp[3];
            }
            #pragma unroll
            for (int mt = 0; mt < 2; mt++)
                #pragma unroll
                for (int nt = 0; nt < 8; nt++) {
                    mma16816(d[mt][nt], ah[mt], bh[nt]);
                    mma16816(d[mt][nt], ah[mt], bl[nt]);
                    mma16816(d[mt][nt], al[mt], bh[nt]);
                }
        }
        __syncthreads();
    }

    // ---- epilogue ----
    int rq = lane >> 2, cq = (lane & 3) * 2;
    #pragma unroll
    for (int mt = 0; mt < 2; mt++) {
        int grow0 = m0 + wm * 32 + mt * 16 + rq;
        #pragma unroll
        for (int nt = 0; nt < 8; nt++) {
            int gcol = n0 + wn * 64 + nt * 8 + cq;
            float2 bv = make_float2(0.f, 0.f);
            if (bias) bv = *(const float2*)(bias + gcol);
            float2 o0 = make_float2(d[mt][nt][0] + bv.x, d[mt][nt][1] + bv.y);
            float2 o1 = make_float2(d[mt][nt][2] + bv.x, d[mt][nt][3] + bv.y);
            if (doRelu) {
                o0.x = fmaxf(o0.x, 0.f); o0.y = fmaxf(o0.y, 0.f);
                o1.x = fmaxf(o1.x, 0.f); o1.y = fmaxf(o1.y, 0.f);
            }
            if (grow0 < M)     *(float2*)(C + (size_t)grow0 * Ncols + gcol) = o0;
            if (grow0 + 8 < M) *(float2*)(C + (size_t)(grow0 + 8) * Ncols + gcol) = o1;
        }
    }
}

// ---------------- utility kernels ----------------
__global__ void k_zero() {
    int i = blockIdx.x * blockDim.x + threadIdx.x;
    if (i < N_NODES) { g_deg[i] = 0.f; g_cnt[i] = 0; g_cur[i] = 0; }
    if (i < 2 * HID) { g_stats1[i] = 0.f; g_stats2[i] = 0.f; }
    if (i < NC0 * HID) g_xp0[i] = 0.f;
    if (i < NC0 * NC0) g_A0[i] = 0.f;
}

__global__ void k_count(const int* __restrict__ col, const float* __restrict__ ew) {
    int e = blockIdx.x * blockDim.x + threadIdx.x;
    if (e >= N_EDGES) return;
    int c = col[e];
    atomicAdd(&g_cnt[c], 1);
    atomicAdd(&g_deg[c], ew[e]);
}

__global__ void k_scan() {
    __shared__ int sh[1024];
    const int PER = 10;
    int t = threadIdx.x;
    int base = t * PER;
    int loc[PER];
    int s = 0;
    #pragma unroll
    for (int p = 0; p < PER; p++) {
        int idx = base + p;
        int v = (idx < N_NODES) ? g_cnt[idx] : 0;
        loc[p] = s; s += v;
    }
    sh[t] = s; __syncthreads();
    for (int off = 1; off < 1024; off <<= 1) {
        int v = (t >= off) ? sh[t - off] : 0;
        __syncthreads();
        sh[t] += v;
        __syncthreads();
    }
    int excl = (t == 0) ? 0 : sh[t - 1];
    #pragma unroll
    for (int p = 0; p < PER; p++) {
        int idx = base + p;
        if (idx < N_NODES) g_offs[idx] = excl + loc[p];
    }
    if (t == 1023) g_offs[N_NODES] = sh[1023];
}

__global__ void k_fill(const int* __restrict__ col) {
    int e = blockIdx.x * blockDim.x + threadIdx.x;
    if (e < N_NODES) g_deg[e] = rsqrtf(g_deg[e] + 1.0f);
    if (e >= N_EDGES) return;
    int c = col[e];
    int p = atomicAdd(&g_cur[c], 1);
    g_perm[g_offs[c] + p] = e;
}

// ---------------- GCN aggregation + fused BN stats ----------------
__global__ void k_gcn(const float* __restrict__ hlin, const float* __restrict__ bias,
                      const int* __restrict__ row, const float* __restrict__ ew,
                      float* __restrict__ pre, float* __restrict__ stats)
{
    __shared__ float sS[HID], sQ[HID];
    int t = threadIdx.x;
    if (t < HID) { sS[t] = 0.f; sQ[t] = 0.f; }
    __syncthreads();
    int warp = t >> 5, lane = t & 31;
    int i = blockIdx.x * 8 + warp;
    if (i < N_NODES) {
        float di = g_deg[i];
        int s = g_offs[i], epnd = g_offs[i + 1];
        float4 acc = make_float4(0.f, 0.f, 0.f, 0.f);
        for (int idx = s; idx < epnd; idx++) {
            int e = g_perm[idx];
            int r = row[e];
            float nrm = g_deg[r] * ew[e] * di;
            float4 v = *(const float4*)(hlin + (size_t)r * HID + lane * 4);
            acc.x += nrm * v.x; acc.y += nrm * v.y;
            acc.z += nrm * v.z; acc.w += nrm * v.w;
        }
        float4 hs = *(const float4*)(hlin + (size_t)i * HID + lane * 4);
        float sl = di * di;
        float4 b4 = *(const float4*)(bias + lane * 4);
        float4 o;
        o.x = fmaxf(acc.x + hs.x * sl + b4.x, 0.f);
        o.y = fmaxf(acc.y + hs.y * sl + b4.y, 0.f);
        o.z = fmaxf(acc.z + hs.z * sl + b4.z, 0.f);
        o.w = fmaxf(acc.w + hs.w * sl + b4.w, 0.f);
        *(float4*)(pre + (size_t)i * HID + lane * 4) = o;
        int f = lane * 4;
        atomicAdd(&sS[f + 0], o.x); atomicAdd(&sQ[f + 0], o.x * o.x);
        atomicAdd(&sS[f + 1], o.y); atomicAdd(&sQ[f + 1], o.y * o.y);
        atomicAdd(&sS[f + 2], o.z); atomicAdd(&sQ[f + 2], o.z * o.z);
        atomicAdd(&sS[f + 3], o.w); atomicAdd(&sQ[f + 3], o.w * o.w);
    }
    __syncthreads();
    if (t < HID) {
        atomicAdd(&stats[t], sS[t]);
        atomicAdd(&stats[HID + t], sQ[t]);
    }
}

__global__ void k_bnfinal(const float* __restrict__ stats,
                          const float* __restrict__ g, const float* __restrict__ b,
                          float* __restrict__ scale, float* __restrict__ shift) {
    int j = threadIdx.x;
    float m = stats[j] / (float)N_NODES;
    float var = stats[HID + j] / (float)N_NODES - m * m;
    float sc = g[j] * rsqrtf(var + 1e-5f);
    scale[j] = sc;
    shift[j] = b[j] - m * sc;
}

// ---------------- level-0 assignment + fused xp0 ----------------
__global__ void k_assign0(const float* __restrict__ w, const float* __restrict__ bias,
                          const float* __restrict__ gum) {
    __shared__ float sW[NC0][HID];
    __shared__ float sAcc[NC0][HID];
    int t = threadIdx.x;
    for (int i = t; i < HID * NC0; i += 256) {
        int k = i / NC0, c = i % NC0;
        sW[c][k] = w[i];
        ((float*)sAcc)[i] = 0.f;
    }
    __syncthreads();
    int warp = t >> 5, lane = t & 31;
    for (int n = blockIdx.x * 8 + warp; n < N_NODES; n += gridDim.x * 8) {
        float4 xv = *(const float4*)(g_bottom + (size_t)n * HID + lane * 4);
        float best = -1e30f; int bi = 0;
        #pragma unroll
        for (int c = 0; c < NC0; c++) {
            float4 wv = *(float4*)&sW[c][lane * 4];
            float p = xv.x * wv.x + xv.y * wv.y + xv.z * wv.z + xv.w * wv.w;
            #pragma unroll
            for (int off = 16; off > 0; off >>= 1)
                p += __shfl_xor_sync(0xffffffffu, p, off);
            p += bias[c] + gum[(size_t)n * NC0 + c];
            if (p > best) { best = p; bi = c; }
        }
        if (lane == 0) g_c0[n] = bi;
        int f = lane * 4;
        atomicAdd(&sAcc[bi][f + 0], xv.x);
        atomicAdd(&sAcc[bi][f + 1], xv.y);
        atomicAdd(&sAcc[bi][f + 2], xv.z);
        atomicAdd(&sAcc[bi][f + 3], xv.w);
    }
    __syncthreads();
    for (int i = t; i < NC0 * HID; i += 256)
        atomicAdd(&g_xp0[i], ((float*)sAcc)[i]);
}

__global__ void k_A0(const int* __restrict__ row, const int* __restrict__ col,
                     const float* __restrict__ ew) {
    __shared__ float sA[NC0 * NC0];
    int t = threadIdx.x;
    if (t < NC0 * NC0) sA[t] = 0.f;
    __syncthreads();
    for (int e = blockIdx.x * blockDim.x + t; e < N_EDGES; e += gridDim.x * blockDim.x)
        atomicAdd(&sA[g_c0[row[e]] * NC0 + g_c0[col[e]]], ew[e]);
    __syncthreads();
    if (t < NC0 * NC0) atomicAdd(&g_A0[t], sA[t]);
}

// ---------------- tiny hierarchical pooling math ----------------
__device__ __forceinline__ float blockReduce128(float v, float* red) {
    int t = threadIdx.x;
    red[t] = v; __syncthreads();
    #pragma unroll
    for (int off = 64; off > 0; off >>= 1) {
        if (t < off) red[t] += red[t + off];
        __syncthreads();
    }
    float r = red[0]; __syncthreads();
    return r;
}

__global__ void k_levels(const float* __restrict__ me0_w, const float* __restrict__ me0_b,
                         const float* __restrict__ ml1_w, const float* __restrict__ ml1_b,
                         const float* __restrict__ gum1,
                         const float* __restrict__ me1_w, const float* __restrict__ me1_b)
{
    __shared__ float sA0[NC0 * NC0];
    __shared__ float sXp[NC0][HID];
    __shared__ float sM[NC0][HID];
    __shared__ float sL0[NC0][HID];
    __shared__ float sXp1[NC1][HID];
    __shared__ float sM1[NC1][HID];
    __shared__ float red[HID];
    __shared__ float sZ[NC0][NC1];
    __shared__ float sA1[NC1 * NC1];
    __shared__ int   sC1[NC0];
    int t = threadIdx.x;

    float a = (t < NC0 * NC0) ? g_A0[t] : 0.f;
    float S0 = blockReduce128(a, red);
    if (t < NC0 * NC0) sA0[t] = a / S0;
    __syncthreads();

    for (int c = 0; c < NC0; c++) {
        float v = g_xp0[c * HID + t];
        float nsq = blockReduce128(v * v, red);
        float nrm = sqrtf(nsq);
        sXp[c][t] = v / fmaxf(nrm, 1e-12f);
    }
    __syncthreads();

    for (int c = 0; c < NC0; c++) {
        float s = 0.f;
        #pragma unroll
        for (int k = 0; k < NC0; k++) s += sA0[c * NC0 + k] * sXp[k][t];
        sM[c][t] = s;
    }
    __syncthreads();

    {
        float acc[NC0];
        #pragma unroll
        for (int c = 0; c < NC0; c++) acc[c] = me0_b[t];
        for (int k = 0; k < HID; k++) {
            float w = me0_w[k * HID + t];
            #pragma unroll
            for (int c = 0; c < NC0; c++) acc[c] += sM[c][k] * w;
        }
        #pragma unroll
        for (int c = 0; c < NC0; c++) {
            float v = tanhf(acc[c]);
            sL0[c][t] = v;
            g_latent0[c * HID + t] = v;
        }
    }
    __syncthreads();

    if (t < NC0 * NC1) {
        int k = t / NC1, c = t % NC1;
        float s = ml1_b[c] + gum1[k * NC1 + c];
        for (int j = 0; j < HID; j++) s += sL0[k][j] * ml1_w[j * NC1 + c];
        sZ[k][c] = s;
    }
    __syncthreads();
    if (t < NC0) {
        float best = sZ[t][0]; int bi = 0;
        #pragma unroll
        for (int c = 1; c < NC1; c++)
            if (sZ[t][c] > best) { best = sZ[t][c]; bi = c; }
        sC1[t] = bi;
        g_c1[t] = bi;
    }
    __syncthreads();

    for (int c = 0; c < NC1; c++) {
        float v = 0.f;
        #pragma unroll
        for (int k = 0; k < NC0; k++)
            if (sC1[k] == c) v += sL0[k][t];
        float nsq = blockReduce128(v * v, red);
        float nrm = sqrtf(nsq);
        sXp1[c][t] = v / fmaxf(nrm, 1e-12f);
    }
    __syncthreads();

    if (t < NC1 * NC1) {
        int aa = t / NC1, bb = t % NC1;
        float s = 0.f;
        for (int k = 0; k < NC0; k++)
            for (int l = 0; l < NC0; l++)
                if (sC1[k] == aa && sC1[l] == bb) s += sA0[k * NC0 + l];
        sA1[t] = s;
    }
    __syncthreads();
    float a1v = (t < NC1 * NC1) ? sA1[t] : 0.f;
    float S1 = blockReduce128(a1v, red);
    if (t < NC1 * NC1) sA1[t] = a1v / S1;
    __syncthreads();

    for (int c = 0; c < NC1; c++) {
        float s = 0.f;
        #pragma unroll
        for (int k = 0; k < NC1; k++) s += sA1[c * NC1 + k] * sXp1[k][t];
        sM1[c][t] = s;
    }
    __syncthreads();
    {
        float acc[NC1];
        #pragma unroll
        for (int c = 0; c < NC1; c++) acc[c] = me1_b[t];
        for (int k = 0; k < HID; k++) {
            float w = me1_w[k * HID + t];
            #pragma unroll
            for (int c = 0; c < NC1; c++) acc[c] += sM1[c][k] * w;
        }
        #pragma unroll
        for (int c = 0; c < NC1; c++) g_latent1[c * HID + t] = tanhf(acc[c]);
    }
}

// ---------------- final fc2 ----------------
__global__ void k_fc2(const float* __restrict__ w, const float* __restrict__ b,
                      float* __restrict__ out) {
    int warp = (blockIdx.x * blockDim.x + threadIdx.x) >> 5;
    int lane = threadIdx.x & 31;
    if (warp >= N_NODES) return;
    const float4* fp = (const float4*)(g_f1 + (size_t)warp * 512);
    const float4* wp = (const float4*)w;
    float s = 0.f;
    #pragma unroll
    for (int i = lane; i < 128; i += 32) {
        float4 aa = fp[i], cc = wp[i];
        s += aa.x * cc.x + aa.y * cc.y + aa.z * cc.z + aa.w * cc.w;
    }
    #pragma unroll
    for (int off = 16; off > 0; off >>= 1)
        s += __shfl_xor_sync(0xffffffffu, s, off);
    if (lane == 0) out[warp] = fmaxf(s + b[0], 0.f);
}

// ---------------- host ----------------
extern "C" void kernel_launch(void* const* d_in, const int* in_sizes, int n_in,
                              void* d_out, int out_size)
{
    const float* x       = (const float*)d_in[0];
    const float* ew      = (const float*)d_in[1];
    const float* gum0    = (const float*)d_in[2];
    const float* gum1    = (const float*)d_in[3];
    const float* conv1_w = (const float*)d_in[4];
    const float* conv1_b = (const float*)d_in[5];
    const float* conv2_w = (const float*)d_in[6];
    const float* conv2_b = (const float*)d_in[7];
    const float* bn1_g   = (const float*)d_in[8];
    const float* bn1_b   = (const float*)d_in[9];
    const float* bn2_g   = (const float*)d_in[10];
    const float* bn2_b   = (const float*)d_in[11];
    const float* enc1_w  = (const float*)d_in[12];
    const float* enc1_b  = (const float*)d_in[13];
    const float* enc2_w  = (const float*)d_in[14];
    const float* enc2_b  = (const float*)d_in[15];
    const float* ml0_w   = (const float*)d_in[16];
    const float* ml0_b   = (const float*)d_in[17];
    const float* ml1_w   = (const float*)d_in[18];
    const float* ml1_b   = (const float*)d_in[19];
    const float* me0_w   = (const float*)d_in[20];
    const float* me0_b   = (const float*)d_in[21];
    const float* me1_w   = (const float*)d_in[22];
    const float* me1_b   = (const float*)d_in[23];
    const float* fc1_w   = (const float*)d_in[24];
    const float* fc1_b   = (const float*)d_in[25];
    const float* fc2_w   = (const float*)d_in[26];
    const float* fc2_b   = (const float*)d_in[27];
    const int*   ei      = (const int*)d_in[28];
    const int* row = ei;
    const int* col = ei + N_EDGES;
    float* out = (float*)d_out;

    float *p_hlin, *p_pre1, *p_pre2, *p_e1, *p_bottom, *p_f1;
    float *p_stats1, *p_stats2, *p_sc1, *p_sh1, *p_sc2, *p_sh2, *p_lat0, *p_lat1;
    __nv_bfloat16 *p_wh, *p_wl;
    cudaGetSymbolAddress((void**)&p_hlin,   g_hlin);
    cudaGetSymbolAddress((void**)&p_pre1,   g_pre1);
    cudaGetSymbolAddress((void**)&p_pre2,   g_pre2);
    cudaGetSymbolAddress((void**)&p_e1,     g_e1);
    cudaGetSymbolAddress((void**)&p_bottom, g_bottom);
    cudaGetSymbolAddress((void**)&p_f1,     g_f1);
    cudaGetSymbolAddress((void**)&p_stats1, g_stats1);
    cudaGetSymbolAddress((void**)&p_stats2, g_stats2);
    cudaGetSymbolAddress((void**)&p_sc1,    g_sc1);
    cudaGetSymbolAddress((void**)&p_sh1,    g_sh1);
    cudaGetSymbolAddress((void**)&p_sc2,    g_sc2);
    cudaGetSymbolAddress((void**)&p_sh2,    g_sh2);
    cudaGetSymbolAddress((void**)&p_lat0,   g_latent0);
    cudaGetSymbolAddress((void**)&p_lat1,   g_latent1);
    cudaGetSymbolAddress((void**)&p_wh,     g_wh);
    cudaGetSymbolAddress((void**)&p_wl,     g_wl);

    const int GB = (N_NODES + 127) / 128;   // 79
    dim3 g1(GB, 1), g4(GB, 4);

    k_wprep<<<(W_TOTAL + 255) / 256, 256>>>(conv1_w, conv2_w, enc1_w, enc2_w, fc1_w);
    k_zero<<<40, 256>>>();
    k_count<<<(N_EDGES + 255) / 256, 256>>>(col, ew);
    k_scan<<<1, 1024>>>();
    k_fill<<<(N_EDGES + 255) / 256, 256>>>(col);

    // conv1
    tgemm<<<g1, 256>>>(x, nullptr, nullptr,
                       nullptr, nullptr, nullptr, nullptr, nullptr, nullptr,
                       p_wh + WO_CONV1, p_wl + WO_CONV1, nullptr, p_hlin,
                       N_NODES, 1, 128, 0, 0);
    k_gcn<<<1250, 256>>>(p_hlin, conv1_b, row, ew, p_pre1, p_stats1);
    k_bnfinal<<<1, 128>>>(p_stats1, bn1_g, bn1_b, p_sc1, p_sh1);

    // conv2
    tgemm<<<g1, 256>>>(p_pre1, nullptr, nullptr,
                       p_sc1, p_sh1, nullptr, nullptr, nullptr, nullptr,
                       p_wh + WO_CONV2, p_wl + WO_CONV2, nullptr, p_hlin,
                       N_NODES, 1, 128, 0, 0);
    k_gcn<<<1250, 256>>>(p_hlin, conv2_b, row, ew, p_pre2, p_stats2);
    k_bnfinal<<<1, 128>>>(p_stats2, bn2_g, bn2_b, p_sc2, p_sh2);

    // enc1 / enc2
    tgemm<<<g1, 256>>>(x, p_pre1, p_pre2,
                       nullptr, nullptr, p_sc1, p_sh1, p_sc2, p_sh2,
                       p_wh + WO_ENC1, p_wl + WO_ENC1, enc1_b, p_e1,
                       N_NODES, 3, 128, 1, 0);
    tgemm<<<g1, 256>>>(p_e1, nullptr, nullptr,
                       nullptr, nullptr, nullptr, nullptr, nullptr, nullptr,
                       p_wh + WO_ENC2, p_wl + WO_ENC2, enc2_b, p_bottom,
                       N_NODES, 1, 128, 1, 0);

    // hierarchical pooling
    k_assign0<<<80, 256>>>(ml0_w, ml0_b, gum0);
    k_A0<<<120, 256>>>(row, col, ew);
    k_levels<<<1, 128>>>(me0_w, me0_b, ml1_w, ml1_b, gum1, me1_w, me1_b);

    // fc1 + fc2
    tgemm<<<g4, 256>>>(p_bottom, p_lat0, p_lat1,
                       nullptr, nullptr, nullptr, nullptr, nullptr, nullptr,
                       p_wh + WO_FC1, p_wl + WO_FC1, fc1_b, p_f1,
                       N_NODES, 3, 512, 1, 1);
    k_fc2<<<1250, 256>>>(fc2_w, fc2_b, out);
}

// round 5
// speedup vs baseline: 2.3346x; 1.1922x over previous
#include <cuda_runtime.h>
#include <cuda_bf16.h>
#include <stdint.h>
#include <math.h>

#define N_NODES 10000
#define N_EDGES 320000
#define HID 128
#define NC0 10
#define NC1 5

// ---------------- device scratch ----------------
__device__ float g_deg[N_NODES];
__device__ int   g_cnt[N_NODES];
__device__ int   g_cur[N_NODES];
__device__ int   g_offs[N_NODES + 1];
__device__ int   g_srow[N_EDGES];
__device__ float g_sew[N_EDGES];
__device__ float g_hlin[N_NODES * HID];
__device__ float g_pre1[N_NODES * HID];
__device__ float g_pre2[N_NODES * HID];
__device__ float g_e1[N_NODES * HID];
__device__ float g_bottom[N_NODES * HID];
__device__ float g_stats1[2 * HID];
__device__ float g_stats2[2 * HID];
__device__ int   g_c0[N_NODES];
__device__ int   g_c1[NC0];
__device__ float g_xp0[NC0 * HID];
__device__ float g_A0[NC0 * NC0];
__device__ float g_latent0[NC0 * HID];
__device__ float g_latent1[NC1 * HID];

// pre-converted transposed weights [N][K] bf16 hi/lo
#define WO_CONV1 0
#define WO_CONV2 16384
#define WO_ENC1  32768
#define WO_ENC2  81920
#define WO_FC1   98304
#define W_TOTAL  294912
__device__ __align__(16) __nv_bfloat16 g_wh[W_TOTAL];
__device__ __align__(16) __nv_bfloat16 g_wl[W_TOTAL];

// ---------------- PTX wrappers (baseline ISA) ----------------
__device__ __forceinline__ uint32_t smem_u32(const void* p) {
    uint32_t a;
    asm("{ .reg .u64 t; cvta.to.shared.u64 t, %1; cvt.u32.u64 %0, t; }" : "=r"(a) : "l"(p));
    return a;
}
__device__ __forceinline__ void ldsm4(uint32_t r[4], uint32_t addr) {
    asm volatile("ldmatrix.sync.aligned.m8n8.x4.shared.b16 {%0,%1,%2,%3}, [%4];"
        : "=r"(r[0]), "=r"(r[1]), "=r"(r[2]), "=r"(r[3]) : "r"(addr));
}
__device__ __forceinline__ void mma16816(float d[4], const uint32_t a[4], const uint32_t b[2]) {
    asm volatile("mma.sync.aligned.m16n8k16.row.col.f32.bf16.bf16.f32 "
        "{%0,%1,%2,%3}, {%4,%5,%6,%7}, {%8,%9}, {%0,%1,%2,%3};"
        : "+f"(d[0]), "+f"(d[1]), "+f"(d[2]), "+f"(d[3])
        : "r"(a[0]), "r"(a[1]), "r"(a[2]), "r"(a[3]), "r"(b[0]), "r"(b[1]));
}
__device__ __forceinline__ void cp16(uint32_t d, const void* s) {
    asm volatile("cp.async.cg.shared.global [%0], [%1], 16;" :: "r"(d), "l"(s));
}
#define CP_COMMIT() asm volatile("cp.async.commit_group;" ::: "memory")
#define CP_WAIT0()  asm volatile("cp.async.wait_group 0;" ::: "memory")

// swizzled byte offset inside a [rows][32 bf16] tile (row stride 64B)
__device__ __forceinline__ uint32_t swz(int row, int kb) {
    int c = kb >> 4;
    int rem = kb & 15;
    int cp = c ^ ((row >> 1) & 3);
    return (uint32_t)(row * 64 + cp * 16 + rem);
}

// ---------------- weight prep ----------------
__global__ void k_wprep(const float* __restrict__ w1, const float* __restrict__ w2,
                        const float* __restrict__ we1, const float* __restrict__ we2,
                        const float* __restrict__ wf1) {
    int i = blockIdx.x * blockDim.x + threadIdx.x;
    if (i >= W_TOTAL) return;
    const float* w; int K, Nn; int d = i;
    if (d < 16384)       { w = w1;  K = 128; Nn = 128; }
    else if (d < 32768)  { w = w2;  K = 128; Nn = 128; d -= 16384; }
    else if (d < 81920)  { w = we1; K = 384; Nn = 128; d -= 32768; }
    else if (d < 98304)  { w = we2; K = 128; Nn = 128; d -= 81920; }
    else                 { w = wf1; K = 384; Nn = 512; d -= 98304; }
    int n = d / K, k = d % K;
    float v = w[(size_t)k * Nn + n];
    __nv_bfloat16 h = __float2bfloat16(v);
    float l = v - __bfloat162float(h);
    g_wh[i] = h;
    g_wl[i] = __float2bfloat16(l);
}

// ---------------- bf16x3 tensor-core GEMM, 64x128 tile, double-buffered ----------------
// C = act(A @ B + bias). A's K = 128*nseg from up to 3 segments (optional on-the-fly
// BN from raw stats, optional cluster indirection). If w2 != null, instead of storing
// C, dot the relu'd slice with w2 and atomicAdd per-row partials into outAcc.
__global__ __launch_bounds__(256, 2)
void tgemm(const float* __restrict__ A0, const float* __restrict__ A1, const float* __restrict__ A2,
           const float* __restrict__ st0, const float* __restrict__ ga0, const float* __restrict__ be0,
           const float* __restrict__ st1, const float* __restrict__ ga1, const float* __restrict__ be1,
           const float* __restrict__ st2, const float* __restrict__ ga2, const float* __restrict__ be2,
           const __nv_bfloat16* __restrict__ Bh, const __nv_bfloat16* __restrict__ Bl,
           const float* __restrict__ bias, float* __restrict__ C,
           const float* __restrict__ w2, float* __restrict__ outAcc,
           int M, int nseg, int Ncols, int doRelu, int idxmode)
{
    __shared__ __align__(16) char sA[2][2][4096];   // [buf][hi/lo][64 x 64B]
    __shared__ __align__(16) char sB[2][2][8192];   // [buf][hi/lo][128 x 64B]

    int t = threadIdx.x;
    int wid = t >> 5, lane = t & 31;
    int wm = wid >> 1, wn = wid & 1;            // 4 x 2 warps, each 16 x 64
    int m0 = blockIdx.x * 64, n0 = blockIdx.y * 128;

    // A staging: thread handles row t>>2, 8 K-elems at quad (t&3)*8
    int sRow = t >> 2, sQuad = t & 3;
    int gm = m0 + sRow;
    bool mOK = gm < M;
    int gi = mOK ? gm : 0;
    int i1 = gi, i2 = gi;
    if (idxmode && mOK) { i1 = g_c0[gi]; i2 = g_c1[i1]; }
    const float* rp[3];
    rp[0] = A0 ? A0 + (size_t)gi * 128 : (const float*)0;
    rp[1] = A1 ? A1 + (size_t)i1 * 128 : (const float*)0;
    rp[2] = A2 ? A2 + (size_t)i2 * 128 : (const float*)0;
    const float* stp[3] = { st0, st1, st2 };
    const float* gap[3] = { ga0, ga1, ga2 };
    const float* bep[3] = { be0, be1, be2 };

    // B staging: thread handles row t>>1, half (t&1)*16 elems
    int bRow = t >> 1, bHalf = t & 1;

    int Kfull = nseg * 128;
    int nChunks = nseg * 4;                     // 32 K per chunk
    const float invN = 1.0f / (float)N_NODES;

    uint32_t uA[2][2], uB[2][2];
    #pragma unroll
    for (int b = 0; b < 2; b++) {
        uA[b][0] = smem_u32(sA[b][0]); uA[b][1] = smem_u32(sA[b][1]);
        uB[b][0] = smem_u32(sB[b][0]); uB[b][1] = smem_u32(sB[b][1]);
    }

    float4 aPre[2];
    auto ldgA = [&](int ch) {
        int koff = ch * 32;
        int seg = koff >> 7;
        int kin = (koff & 127) + sQuad * 8;
        const float* ap = rp[seg] + kin;
        aPre[0] = mOK ? *(const float4*)(ap + 0) : make_float4(0.f, 0.f, 0.f, 0.f);
        aPre[1] = mOK ? *(const float4*)(ap + 4) : make_float4(0.f, 0.f, 0.f, 0.f);
    };
    auto cvtA = [&](int ch, int buf) {
        int koff = ch * 32;
        int seg = koff >> 7;
        int kin = (koff & 127) + sQuad * 8;
        float f[8] = { aPre[0].x, aPre[0].y, aPre[0].z, aPre[0].w,
                       aPre[1].x, aPre[1].y, aPre[1].z, aPre[1].w };
        if (stp[seg]) {
            const float* st = stp[seg];
            const float* ga = gap[seg];
            const float* be = bep[seg];
            #pragma unroll
            for (int j = 0; j < 8; j++) {
                int k = kin + j;
                float m = st[k] * invN;
                float var = st[HID + k] * invN - m * m;
                float sc = ga[k] * rsqrtf(var + 1e-5f);
                f[j] = f[j] * sc + (be[k] - m * sc);
            }
        }
        uint32_t hi[4], lo[4];
        #pragma unroll
        for (int j = 0; j < 4; j++) {
            __nv_bfloat162 h = __floats2bfloat162_rn(f[j * 2], f[j * 2 + 1]);
            __nv_bfloat162 l = __floats2bfloat162_rn(f[j * 2] - __bfloat162float(h.x),
                                                     f[j * 2 + 1] - __bfloat162float(h.y));
            hi[j] = *(uint32_t*)&h; lo[j] = *(uint32_t*)&l;
        }
        uint32_t sw = swz(sRow, sQuad * 16);
        *(uint4*)(sA[buf][0] + sw) = make_uint4(hi[0], hi[1], hi[2], hi[3]);
        *(uint4*)(sA[buf][1] + sw) = make_uint4(lo[0], lo[1], lo[2], lo[3]);
    };
    auto cpB = [&](int ch, int buf) {
        int koff = ch * 32;
        size_t g = (size_t)(n0 + bRow) * Kfull + koff + bHalf * 16;
        uint32_t d0 = uB[buf][0] + swz(bRow, bHalf * 32);
        uint32_t d1 = uB[buf][0] + swz(bRow, bHalf * 32 + 16);
        cp16(d0, Bh + g);
        cp16(d1, Bh + g + 8);
        uint32_t e0 = uB[buf][1] + swz(bRow, bHalf * 32);
        uint32_t e1 = uB[buf][1] + swz(bRow, bHalf * 32 + 16);
        cp16(e0, Bl + g);
        cp16(e1, Bl + g + 8);
    };

    float d[8][4];
    #pragma unroll
    for (int a = 0; a < 8; a++)
        #pragma unroll
        for (int b = 0; b < 4; b++) d[a][b] = 0.f;

    // prologue
    ldgA(0); cpB(0, 0); CP_COMMIT();
    cvtA(0, 0);
    CP_WAIT0();
    __syncthreads();

    int mid = lane >> 3, r8 = lane & 7;
    int buf = 0;
    for (int ch = 0; ch < nChunks; ch++) {
        bool more = ch + 1 < nChunks;
        if (more) { ldgA(ch + 1); cpB(ch + 1, buf ^ 1); CP_COMMIT(); }

        #pragma unroll
        for (int kk = 0; kk < 2; kk++) {
            uint32_t ah[4], al[4];
            {
                int arow = wm * 16 + (mid & 1) * 8 + r8;
                uint32_t kb = (uint32_t)(kk * 32 + (mid >> 1) * 16);
                uint32_t sw = swz(arow, kb);
                ldsm4(ah, uA[buf][0] + sw);
                ldsm4(al, uA[buf][1] + sw);
            }
            uint32_t bh[8][2], bl[8][2];
            #pragma unroll
            for (int ntp = 0; ntp < 4; ntp++) {
                int brow = wn * 64 + ntp * 16 + (mid >> 1) * 8 + r8;
                uint32_t kb = (uint32_t)(kk * 32 + (mid & 1) * 16);
                uint32_t sw = swz(brow, kb);
                uint32_t tmp[4];
                ldsm4(tmp, uB[buf][0] + sw);
                bh[ntp * 2 + 0][0] = tmp[0]; bh[ntp * 2 + 0][1] = tmp[1];
                bh[ntp * 2 + 1][0] = tmp[2]; bh[ntp * 2 + 1][1] = tmp[3];
                ldsm4(tmp, uB[buf][1] + sw);
                bl[ntp * 2 + 0][0] = tmp[0]; bl[ntp * 2 + 0][1] = tmp[1];
                bl[ntp * 2 + 1][0] = tmp[2]; bl[ntp * 2 + 1][1] = tmp[3];
            }
            #pragma unroll
            for (int nt = 0; nt < 8; nt++) {
                mma16816(d[nt], ah, bh[nt]);
                mma16816(d[nt], ah, bl[nt]);
                mma16816(d[nt], al, bh[nt]);
            }
        }

        if (more) { cvtA(ch + 1, buf ^ 1); CP_WAIT0(); }
        __syncthreads();
        buf ^= 1;
    }

    // ---- epilogue ----
    int rq = lane >> 2, cq = (lane & 3) * 2;
    int grow0 = m0 + wm * 16 + rq;
    if (w2) {
        float p0 = 0.f, p1 = 0.f;
        #pragma unroll
        for (int nt = 0; nt < 8; nt++) {
            int gcol = n0 + wn * 64 + nt * 8 + cq;
            float2 bv = *(const float2*)(bias + gcol);
            float o0x = fmaxf(d[nt][0] + bv.x, 0.f), o0y = fmaxf(d[nt][1] + bv.y, 0.f);
            float o1x = fmaxf(d[nt][2] + bv.x, 0.f), o1y = fmaxf(d[nt][3] + bv.y, 0.f);
            float2 wv = *(const float2*)(w2 + gcol);
            p0 += o0x * wv.x + o0y * wv.y;
            p1 += o1x * wv.x + o1y * wv.y;
        }
        p0 += __shfl_xor_sync(0xffffffffu, p0, 1);
        p0 += __shfl_xor_sync(0xffffffffu, p0, 2);
        p1 += __shfl_xor_sync(0xffffffffu, p1, 1);
        p1 += __shfl_xor_sync(0xffffffffu, p1, 2);
        if ((lane & 3) == 0) {
            if (grow0 < M)     atomicAdd(&outAcc[grow0], p0);
            if (grow0 + 8 < M) atomicAdd(&outAcc[grow0 + 8], p1);
        }
    } else {
        #pragma unroll
        for (int nt = 0; nt < 8; nt++) {
            int gcol = n0 + wn * 64 + nt * 8 + cq;
            float2 bv = make_float2(0.f, 0.f);
            if (bias) bv = *(const float2*)(bias + gcol);
            float2 o0 = make_float2(d[nt][0] + bv.x, d[nt][1] + bv.y);
            float2 o1 = make_float2(d[nt][2] + bv.x, d[nt][3] + bv.y);
            if (doRelu) {
                o0.x = fmaxf(o0.x, 0.f); o0.y = fmaxf(o0.y, 0.f);
                o1.x = fmaxf(o1.x, 0.f); o1.y = fmaxf(o1.y, 0.f);
            }
            if (grow0 < M)     *(float2*)(C + (size_t)grow0 * Ncols + gcol) = o0;
            if (grow0 + 8 < M) *(float2*)(C + (size_t)(grow0 + 8) * Ncols + gcol) = o1;
        }
    }
}

// ---------------- utility kernels ----------------
__global__ void k_zero(float* __restrict__ out) {
    int i = blockIdx.x * blockDim.x + threadIdx.x;
    if (i < N_NODES) { g_deg[i] = 0.f; g_cnt[i] = 0; g_cur[i] = 0; out[i] = 0.f; }
    if (i < 2 * HID) { g_stats1[i] = 0.f; g_stats2[i] = 0.f; }
    if (i < NC0 * HID) g_xp0[i] = 0.f;
    if (i < NC0 * NC0) g_A0[i] = 0.f;
}

__global__ void k_count(const int* __restrict__ col, const float* __restrict__ ew) {
    int e = blockIdx.x * blockDim.x + threadIdx.x;
    if (e >= N_EDGES) return;
    int c = col[e];
    atomicAdd(&g_cnt[c], 1);
    atomicAdd(&g_deg[c], ew[e]);
}

__global__ void k_scan() {
    __shared__ int sh[1024];
    const int PER = 10;
    int t = threadIdx.x;
    int base = t * PER;
    int loc[PER];
    int s = 0;
    #pragma unroll
    for (int p = 0; p < PER; p++) {
        int idx = base + p;
        int v = (idx < N_NODES) ? g_cnt[idx] : 0;
        loc[p] = s; s += v;
    }
    sh[t] = s; __syncthreads();
    for (int off = 1; off < 1024; off <<= 1) {
        int v = (t >= off) ? sh[t - off] : 0;
        __syncthreads();
        sh[t] += v;
        __syncthreads();
    }
    int excl = (t == 0) ? 0 : sh[t - 1];
    #pragma unroll
    for (int p = 0; p < PER; p++) {
        int idx = base + p;
        if (idx < N_NODES) g_offs[idx] = excl + loc[p];
    }
    if (t == 1023) g_offs[N_NODES] = sh[1023];
}

__global__ void k_fill(const int* __restrict__ row, const int* __restrict__ col,
                       const float* __restrict__ ew) {
    int e = blockIdx.x * blockDim.x + threadIdx.x;
    if (e < N_NODES) g_deg[e] = rsqrtf(g_deg[e] + 1.0f);
    if (e >= N_EDGES) return;
    int c = col[e];
    int p = atomicAdd(&g_cur[c], 1);
    int dst = g_offs[c] + p;
    g_srow[dst] = row[e];
    g_sew[dst]  = ew[e];
}

// ---------------- GCN aggregation + fused BN stats ----------------
__global__ void k_gcn(const float* __restrict__ hlin, const float* __restrict__ bias,
                      float* __restrict__ pre, float* __restrict__ stats)
{
    __shared__ float sS[HID], sQ[HID];
    int t = threadIdx.x;
    if (t < HID) { sS[t] = 0.f; sQ[t] = 0.f; }
    __syncthreads();
    int warp = t >> 5, lane = t & 31;
    int i = blockIdx.x * 8 + warp;
    if (i < N_NODES) {
        float di = g_deg[i];
        int s = g_offs[i], epnd = g_offs[i + 1];
        float4 acc = make_float4(0.f, 0.f, 0.f, 0.f);
        for (int idx = s; idx < epnd; idx++) {
            int r = g_srow[idx];
            float nrm = g_deg[r] * g_sew[idx] * di;
            float4 v = *(const float4*)(hlin + (size_t)r * HID + lane * 4);
            acc.x += nrm * v.x; acc.y += nrm * v.y;
            acc.z += nrm * v.z; acc.w += nrm * v.w;
        }
        float4 hs = *(const float4*)(hlin + (size_t)i * HID + lane * 4);
        float sl = di * di;
        float4 b4 = *(const float4*)(bias + lane * 4);
        float4 o;
        o.x = fmaxf(acc.x + hs.x * sl + b4.x, 0.f);
        o.y = fmaxf(acc.y + hs.y * sl + b4.y, 0.f);
        o.z = fmaxf(acc.z + hs.z * sl + b4.z, 0.f);
        o.w = fmaxf(acc.w + hs.w * sl + b4.w, 0.f);
        *(float4*)(pre + (size_t)i * HID + lane * 4) = o;
        int f = lane * 4;
        atomicAdd(&sS[f + 0], o.x); atomicAdd(&sQ[f + 0], o.x * o.x);
        atomicAdd(&sS[f + 1], o.y); atomicAdd(&sQ[f + 1], o.y * o.y);
        atomicAdd(&sS[f + 2], o.z); atomicAdd(&sQ[f + 2], o.z * o.z);
        atomicAdd(&sS[f + 3], o.w); atomicAdd(&sQ[f + 3], o.w * o.w);
    }
    __syncthreads();
    if (t < HID) {
        atomicAdd(&stats[t], sS[t]);
        atomicAdd(&stats[HID + t], sQ[t]);
    }
}

// ---------------- level-0 assignment + fused xp0 ----------------
__global__ void k_assign0(const float* __restrict__ w, const float* __restrict__ bias,
                          const float* __restrict__ gum) {
    __shared__ float sW[NC0][HID];
    __shared__ float sAcc[NC0][HID];
    int t = threadIdx.x;
    for (int i = t; i < HID * NC0; i += 256) {
        int k = i / NC0, c = i % NC0;
        sW[c][k] = w[i];
        ((float*)sAcc)[i] = 0.f;
    }
    __syncthreads();
    int warp = t >> 5, lane = t & 31;
    for (int n = blockIdx.x * 8 + warp; n < N_NODES; n += gridDim.x * 8) {
        float4 xv = *(const float4*)(g_bottom + (size_t)n * HID + lane * 4);
        float best = -1e30f; int bi = 0;
        #pragma unroll
        for (int c = 0; c < NC0; c++) {
            float4 wv = *(float4*)&sW[c][lane * 4];
            float p = xv.x * wv.x + xv.y * wv.y + xv.z * wv.z + xv.w * wv.w;
            #pragma unroll
            for (int off = 16; off > 0; off >>= 1)
                p += __shfl_xor_sync(0xffffffffu, p, off);
            p += bias[c] + gum[(size_t)n * NC0 + c];
            if (p > best) { best = p; bi = c; }
        }
        if (lane == 0) g_c0[n] = bi;
        int f = lane * 4;
        atomicAdd(&sAcc[bi][f + 0], xv.x);
        atomicAdd(&sAcc[bi][f + 1], xv.y);
        atomicAdd(&sAcc[bi][f + 2], xv.z);
        atomicAdd(&sAcc[bi][f + 3], xv.w);
    }
    __syncthreads();
    for (int i = t; i < NC0 * HID; i += 256)
        atomicAdd(&g_xp0[i], ((float*)sAcc)[i]);
}

__global__ void k_A0(const int* __restrict__ row, const int* __restrict__ col,
                     const float* __restrict__ ew) {
    __shared__ float sA[NC0 * NC0];
    int t = threadIdx.x;
    if (t < NC0 * NC0) sA[t] = 0.f;
    __syncthreads();
    for (int e = blockIdx.x * blockDim.x + t; e < N_EDGES; e += gridDim.x * blockDim.x)
        atomicAdd(&sA[g_c0[row[e]] * NC0 + g_c0[col[e]]], ew[e]);
    __syncthreads();
    if (t < NC0 * NC0) atomicAdd(&g_A0[t], sA[t]);
}

// ---------------- tiny hierarchical pooling math ----------------
__device__ __forceinline__ float blockReduce128(float v, float* red) {
    int t = threadIdx.x;
    red[t] = v; __syncthreads();
    #pragma unroll
    for (int off = 64; off > 0; off >>= 1) {
        if (t < off) red[t] += red[t + off];
        __syncthreads();
    }
    float r = red[0]; __syncthreads();
    return r;
}

__global__ void k_levels(const float* __restrict__ me0_w, const float* __restrict__ me0_b,
                         const float* __restrict__ ml1_w, const float* __restrict__ ml1_b,
                         const float* __restrict__ gum1,
                         const float* __restrict__ me1_w, const float* __restrict__ me1_b)
{
    __shared__ float sA0[NC0 * NC0];
    __shared__ float sXp[NC0][HID];
    __shared__ float sM[NC0][HID];
    __shared__ float sL0[NC0][HID];
    __shared__ float sXp1[NC1][HID];
    __shared__ float sM1[NC1][HID];
    __shared__ float red[HID];
    __shared__ float sZ[NC0][NC1];
    __shared__ float sA1[NC1 * NC1];
    __shared__ int   sC1[NC0];
    int t = threadIdx.x;

    float a = (t < NC0 * NC0) ? g_A0[t] : 0.f;
    float S0 = blockReduce128(a, red);
    if (t < NC0 * NC0) sA0[t] = a / S0;
    __syncthreads();

    for (int c = 0; c < NC0; c++) {
        float v = g_xp0[c * HID + t];
        float nsq = blockReduce128(v * v, red);
        float nrm = sqrtf(nsq);
        sXp[c][t] = v / fmaxf(nrm, 1e-12f);
    }
    __syncthreads();

    for (int c = 0; c < NC0; c++) {
        float s = 0.f;
        #pragma unroll
        for (int k = 0; k < NC0; k++) s += sA0[c * NC0 + k] * sXp[k][t];
        sM[c][t] = s;
    }
    __syncthreads();

    {
        float acc[NC0];
        #pragma unroll
        for (int c = 0; c < NC0; c++) acc[c] = me0_b[t];
        for (int k = 0; k < HID; k++) {
            float w = me0_w[k * HID + t];
            #pragma unroll
            for (int c = 0; c < NC0; c++) acc[c] += sM[c][k] * w;
        }
        #pragma unroll
        for (int c = 0; c < NC0; c++) {
            float v = tanhf(acc[c]);
            sL0[c][t] = v;
            g_latent0[c * HID + t] = v;
        }
    }
    __syncthreads();

    if (t < NC0 * NC1) {
        int k = t / NC1, c = t % NC1;
        float s = ml1_b[c] + gum1[k * NC1 + c];
        for (int j = 0; j < HID; j++) s += sL0[k][j] * ml1_w[j * NC1 + c];
        sZ[k][c] = s;
    }
    __syncthreads();
    if (t < NC0) {
        float best = sZ[t][0]; int bi = 0;
        #pragma unroll
        for (int c = 1; c < NC1; c++)
            if (sZ[t][c] > best) { best = sZ[t][c]; bi = c; }
        sC1[t] = bi;
        g_c1[t] = bi;
    }
    __syncthreads();

    for (int c = 0; c < NC1; c++) {
        float v = 0.f;
        #pragma unroll
        for (int k = 0; k < NC0; k++)
            if (sC1[k] == c) v += sL0[k][t];
        float nsq = blockReduce128(v * v, red);
        float nrm = sqrtf(nsq);
        sXp1[c][t] = v / fmaxf(nrm, 1e-12f);
    }
    __syncthreads();

    if (t < NC1 * NC1) {
        int aa = t / NC1, bb = t % NC1;
        float s = 0.f;
        for (int k = 0; k < NC0; k++)
            for (int l = 0; l < NC0; l++)
                if (sC1[k] == aa && sC1[l] == bb) s += sA0[k * NC0 + l];
        sA1[t] = s;
    }
    __syncthreads();
    float a1v = (t < NC1 * NC1) ? sA1[t] : 0.f;
    float S1 = blockReduce128(a1v, red);
    if (t < NC1 * NC1) sA1[t] = a1v / S1;
    __syncthreads();

    for (int c = 0; c < NC1; c++) {
        float s = 0.f;
        #pragma unroll
        for (int k = 0; k < NC1; k++) s += sA1[c * NC1 + k] * sXp1[k][t];
        sM1[c][t] = s;
    }
    __syncthreads();
    {
        float acc[NC1];
        #pragma unroll
        for (int c = 0; c < NC1; c++) acc[c] = me1_b[t];
        for (int k = 0; k < HID; k++) {
            float w = me1_w[k * HID + t];
            #pragma unroll
            for (int c = 0; c < NC1; c++) acc[c] += sM1[c][k] * w;
        }
        #pragma unroll
        for (int c = 0; c < NC1; c++) g_latent1[c * HID + t] = tanhf(acc[c]);
    }
}

// ---------------- final bias + relu ----------------
__global__ void k_fin(float* __restrict__ out, const float* __restrict__ b) {
    int i = blockIdx.x * blockDim.x + threadIdx.x;
    if (i < N_NODES) out[i] = fmaxf(out[i] + b[0], 0.f);
}

// ---------------- host ----------------
extern "C" void kernel_launch(void* const* d_in, const int* in_sizes, int n_in,
                              void* d_out, int out_size)
{
    const float* x       = (const float*)d_in[0];
    const float* ew      = (const float*)d_in[1];
    const float* gum0    = (const float*)d_in[2];
    const float* gum1    = (const float*)d_in[3];
    const float* conv1_w = (const float*)d_in[4];
    const float* conv1_b = (const float*)d_in[5];
    const float* conv2_w = (const float*)d_in[6];
    const float* conv2_b = (const float*)d_in[7];
    const float* bn1_g   = (const float*)d_in[8];
    const float* bn1_b   = (const float*)d_in[9];
    const float* bn2_g   = (const float*)d_in[10];
    const float* bn2_b   = (const float*)d_in[11];
    const float* enc1_w  = (const float*)d_in[12];
    const float* enc1_b  = (const float*)d_in[13];
    const float* enc2_w  = (const float*)d_in[14];
    const float* enc2_b  = (const float*)d_in[15];
    const float* ml0_w   = (const float*)d_in[16];
    const float* ml0_b   = (const float*)d_in[17];
    const float* ml1_w   = (const float*)d_in[18];
    const float* ml1_b   = (const float*)d_in[19];
    const float* me0_w   = (const float*)d_in[20];
    const float* me0_b   = (const float*)d_in[21];
    const float* me1_w   = (const float*)d_in[22];
    const float* me1_b   = (const float*)d_in[23];
    const float* fc1_w   = (const float*)d_in[24];
    const float* fc1_b   = (const float*)d_in[25];
    const float* fc2_w   = (const float*)d_in[26];
    const float* fc2_b   = (const float*)d_in[27];
    const int*   ei      = (const int*)d_in[28];
    const int* row = ei;
    const int* col = ei + N_EDGES;
    float* out = (float*)d_out;

    float *p_hlin, *p_pre1, *p_pre2, *p_e1, *p_bottom;
    float *p_stats1, *p_stats2, *p_lat0, *p_lat1;
    __nv_bfloat16 *p_wh, *p_wl;
    cudaGetSymbolAddress((void**)&p_hlin,   g_hlin);
    cudaGetSymbolAddress((void**)&p_pre1,   g_pre1);
    cudaGetSymbolAddress((void**)&p_pre2,   g_pre2);
    cudaGetSymbolAddress((void**)&p_e1,     g_e1);
    cudaGetSymbolAddress((void**)&p_bottom, g_bottom);
    cudaGetSymbolAddress((void**)&p_stats1, g_stats1);
    cudaGetSymbolAddress((void**)&p_stats2, g_stats2);
    cudaGetSymbolAddress((void**)&p_lat0,   g_latent0);
    cudaGetSymbolAddress((void**)&p_lat1,   g_latent1);
    cudaGetSymbolAddress((void**)&p_wh,     g_wh);
    cudaGetSymbolAddress((void**)&p_wl,     g_wl);

    const int GB = (N_NODES + 63) / 64;   // 157
    dim3 g1(GB, 1), g4(GB, 4);

    k_wprep<<<(W_TOTAL + 255) / 256, 256>>>(conv1_w, conv2_w, enc1_w, enc2_w, fc1_w);
    k_zero<<<40, 256>>>(out);
    k_count<<<(N_EDGES + 255) / 256, 256>>>(col, ew);
    k_scan<<<1, 1024>>>();
    k_fill<<<(N_EDGES + 255) / 256, 256>>>(row, col, ew);

    // conv1: hlin = x @ conv1_w
    tgemm<<<g1, 256>>>(x, nullptr, nullptr,
                       nullptr, nullptr, nullptr, nullptr, nullptr, nullptr,
                       nullptr, nullptr, nullptr,
                       p_wh + WO_CONV1, p_wl + WO_CONV1, nullptr, p_hlin,
                       nullptr, nullptr, N_NODES, 1, 128, 0, 0);
    k_gcn<<<1250, 256>>>(p_hlin, conv1_b, p_pre1, p_stats1);

    // conv2: hlin = bn1(pre1) @ conv2_w   (BN computed on the fly from stats1)
    tgemm<<<g1, 256>>>(p_pre1, nullptr, nullptr,
                       p_stats1, bn1_g, bn1_b, nullptr, nullptr, nullptr,
                       nullptr, nullptr, nullptr,
                       p_wh + WO_CONV2, p_wl + WO_CONV2, nullptr, p_hlin,
                       nullptr, nullptr, N_NODES, 1, 128, 0, 0);
    k_gcn<<<1250, 256>>>(p_hlin, conv2_b, p_pre2, p_stats2);

    // enc1: e1 = relu([x | bn1(pre1) | bn2(pre2)] @ enc1_w + b)
    tgemm<<<g1, 256>>>(x, p_pre1, p_pre2,
                       nullptr, nullptr, nullptr,
                       p_stats1, bn1_g, bn1_b,
                       p_stats2, bn2_g, bn2_b,
                       p_wh + WO_ENC1, p_wl + WO_ENC1, enc1_b, p_e1,
                       nullptr, nullptr, N_NODES, 3, 128, 1, 0);
    // enc2
    tgemm<<<g1, 256>>>(p_e1, nullptr, nullptr,
                       nullptr, nullptr, nullptr, nullptr, nullptr, nullptr,
                       nullptr, nullptr, nullptr,
                       p_wh + WO_ENC2, p_wl + WO_ENC2, enc2_b, p_bottom,
                       nullptr, nullptr, N_NODES, 1, 128, 1, 0);

    // hierarchical pooling
    k_assign0<<<80, 256>>>(ml0_w, ml0_b, gum0);
    k_A0<<<120, 256>>>(row, col, ew);
    k_levels<<<1, 128>>>(me0_w, me0_b, ml1_w, ml1_b, gum1, me1_w, me1_b);

    // fc1 with fused fc2 partial-dot epilogue
    tgemm<<<g4, 256>>>(p_bottom, p_lat0, p_lat1,
                       nullptr, nullptr, nullptr, nullptr, nullptr, nullptr,
                       nullptr, nullptr, nullptr,
                       p_wh + WO_FC1, p_wl + WO_FC1, fc1_b, nullptr,
                       fc2_w, out, N_NODES, 3, 512, 1, 1);
    k_fin<<<(N_NODES + 255) / 256, 256>>>(out, fc2_b);
}

// round 6
// speedup vs baseline: 2.3513x; 1.0072x over previous
#include <cuda_runtime.h>
#include <cuda_bf16.h>
#include <stdint.h>
#include <math.h>

#define N_NODES 10000
#define N_EDGES 320000
#define HID 128
#define NC0 10
#define NC1 5

// ---------------- device scratch ----------------
__device__ float g_deg[N_NODES];
__device__ int   g_cnt[N_NODES];
__device__ int   g_cur[N_NODES];
__device__ int   g_offs[N_NODES + 1];
__device__ int   g_srow[N_EDGES];
__device__ float g_sew[N_EDGES];
__device__ float g_hlin[N_NODES * HID];
__device__ float g_pre1[N_NODES * HID];
__device__ float g_pre2[N_NODES * HID];
__device__ float g_e1[N_NODES * HID];
__device__ float g_bottom[N_NODES * HID];
__device__ float g_stats1[2 * HID];
__device__ float g_stats2[2 * HID];
__device__ int   g_c0[N_NODES];
__device__ int   g_c1[NC0];
__device__ float g_xp0[NC0 * HID];
__device__ float g_A0[NC0 * NC0];
__device__ float g_latent0[NC0 * HID];
__device__ float g_latent1[NC1 * HID];

// pre-converted transposed weights [N][K] bf16 hi/lo
#define WO_CONV1 0
#define WO_CONV2 16384
#define WO_ENC1  32768
#define WO_ENC2  81920
#define WO_FC1   98304
#define W_TOTAL  294912
__device__ __align__(16) __nv_bfloat16 g_wh[W_TOTAL];
__device__ __align__(16) __nv_bfloat16 g_wl[W_TOTAL];

// ---------------- PTX wrappers (baseline ISA) ----------------
__device__ __forceinline__ uint32_t smem_u32(const void* p) {
    uint32_t a;
    asm("{ .reg .u64 t; cvta.to.shared.u64 t, %1; cvt.u32.u64 %0, t; }" : "=r"(a) : "l"(p));
    return a;
}
__device__ __forceinline__ void ldsm4(uint32_t r[4], uint32_t addr) {
    asm volatile("ldmatrix.sync.aligned.m8n8.x4.shared.b16 {%0,%1,%2,%3}, [%4];"
        : "=r"(r[0]), "=r"(r[1]), "=r"(r[2]), "=r"(r[3]) : "r"(addr));
}
__device__ __forceinline__ void mma16816(float d[4], const uint32_t a[4], const uint32_t b[2]) {
    asm volatile("mma.sync.aligned.m16n8k16.row.col.f32.bf16.bf16.f32 "
        "{%0,%1,%2,%3}, {%4,%5,%6,%7}, {%8,%9}, {%0,%1,%2,%3};"
        : "+f"(d[0]), "+f"(d[1]), "+f"(d[2]), "+f"(d[3])
        : "r"(a[0]), "r"(a[1]), "r"(a[2]), "r"(a[3]), "r"(b[0]), "r"(b[1]));
}
__device__ __forceinline__ void cp16(uint32_t d, const void* s) {
    asm volatile("cp.async.cg.shared.global [%0], [%1], 16;" :: "r"(d), "l"(s));
}
#define CP_COMMIT() asm volatile("cp.async.commit_group;" ::: "memory")
#define CP_WAIT0()  asm volatile("cp.async.wait_group 0;" ::: "memory")

// swizzled byte offset inside a [rows][32 bf16] tile (row stride 64B)
__device__ __forceinline__ uint32_t swz(int row, int kb) {
    int c = kb >> 4;
    int rem = kb & 15;
    int cp = c ^ ((row >> 1) & 3);
    return (uint32_t)(row * 64 + cp * 16 + rem);
}

// ---------------- fused weight prep + state zeroing ----------------
__global__ void k_wz(const float* __restrict__ w1, const float* __restrict__ w2,
                     const float* __restrict__ we1, const float* __restrict__ we2,
                     const float* __restrict__ wf1, float* __restrict__ out) {
    int i = blockIdx.x * blockDim.x + threadIdx.x;
    if (i < N_NODES) { g_deg[i] = 0.f; g_cnt[i] = 0; g_cur[i] = 0; out[i] = 0.f; }
    if (i < 2 * HID) { g_stats1[i] = 0.f; g_stats2[i] = 0.f; }
    if (i < NC0 * HID) g_xp0[i] = 0.f;
    if (i < NC0 * NC0) g_A0[i] = 0.f;
    if (i >= W_TOTAL) return;
    const float* w; int K, Nn; int d = i;
    if (d < 16384)       { w = w1;  K = 128; Nn = 128; }
    else if (d < 32768)  { w = w2;  K = 128; Nn = 128; d -= 16384; }
    else if (d < 81920)  { w = we1; K = 384; Nn = 128; d -= 32768; }
    else if (d < 98304)  { w = we2; K = 128; Nn = 128; d -= 81920; }
    else                 { w = wf1; K = 384; Nn = 512; d -= 98304; }
    int n = d / K, k = d % K;
    float v = w[(size_t)k * Nn + n];
    __nv_bfloat16 h = __float2bfloat16(v);
    float l = v - __bfloat162float(h);
    g_wh[i] = h;
    g_wl[i] = __float2bfloat16(l);
}

// ---------------- bf16x3 tensor-core GEMM, 64x128 tile, double-buffered ----------------
__global__ __launch_bounds__(256, 2)
void tgemm(const float* __restrict__ A0, const float* __restrict__ A1, const float* __restrict__ A2,
           const float* __restrict__ st0, const float* __restrict__ ga0, const float* __restrict__ be0,
           const float* __restrict__ st1, const float* __restrict__ ga1, const float* __restrict__ be1,
           const float* __restrict__ st2, const float* __restrict__ ga2, const float* __restrict__ be2,
           const __nv_bfloat16* __restrict__ Bh, const __nv_bfloat16* __restrict__ Bl,
           const float* __restrict__ bias, float* __restrict__ C,
           const float* __restrict__ w2, float* __restrict__ outAcc,
           int M, int nseg, int Ncols, int doRelu, int idxmode)
{
    __shared__ __align__(16) char sA[2][2][4096];   // [buf][hi/lo][64 x 64B]
    __shared__ __align__(16) char sB[2][2][8192];   // [buf][hi/lo][128 x 64B]

    int t = threadIdx.x;
    int wid = t >> 5, lane = t & 31;
    int wm = wid >> 1, wn = wid & 1;            // 4 x 2 warps, each 16 x 64
    int m0 = blockIdx.x * 64, n0 = blockIdx.y * 128;

    int sRow = t >> 2, sQuad = t & 3;
    int gm = m0 + sRow;
    bool mOK = gm < M;
    int gi = mOK ? gm : 0;
    int i1 = gi, i2 = gi;
    if (idxmode && mOK) { i1 = g_c0[gi]; i2 = g_c1[i1]; }
    const float* rp[3];
    rp[0] = A0 ? A0 + (size_t)gi * 128 : (const float*)0;
    rp[1] = A1 ? A1 + (size_t)i1 * 128 : (const float*)0;
    rp[2] = A2 ? A2 + (size_t)i2 * 128 : (const float*)0;
    const float* stp[3] = { st0, st1, st2 };
    const float* gap[3] = { ga0, ga1, ga2 };
    const float* bep[3] = { be0, be1, be2 };

    int bRow = t >> 1, bHalf = t & 1;

    int Kfull = nseg * 128;
    int nChunks = nseg * 4;
    const float invN = 1.0f / (float)N_NODES;

    uint32_t uA[2][2], uB[2][2];
    #pragma unroll
    for (int b = 0; b < 2; b++) {
        uA[b][0] = smem_u32(sA[b][0]); uA[b][1] = smem_u32(sA[b][1]);
        uB[b][0] = smem_u32(sB[b][0]); uB[b][1] = smem_u32(sB[b][1]);
    }

    float4 aPre[2];
    auto ldgA = [&](int ch) {
        int koff = ch * 32;
        int seg = koff >> 7;
        int kin = (koff & 127) + sQuad * 8;
        const float* ap = rp[seg] + kin;
        aPre[0] = mOK ? *(const float4*)(ap + 0) : make_float4(0.f, 0.f, 0.f, 0.f);
        aPre[1] = mOK ? *(const float4*)(ap + 4) : make_float4(0.f, 0.f, 0.f, 0.f);
    };
    auto cvtA = [&](int ch, int buf) {
        int koff = ch * 32;
        int seg = koff >> 7;
        int kin = (koff & 127) + sQuad * 8;
        float f[8] = { aPre[0].x, aPre[0].y, aPre[0].z, aPre[0].w,
                       aPre[1].x, aPre[1].y, aPre[1].z, aPre[1].w };
        if (stp[seg]) {
            const float* st = stp[seg];
            const float* ga = gap[seg];
            const float* be = bep[seg];
            #pragma unroll
            for (int j = 0; j < 8; j++) {
                int k = kin + j;
                float m = st[k] * invN;
                float var = st[HID + k] * invN - m * m;
                float sc = ga[k] * rsqrtf(var + 1e-5f);
                f[j] = f[j] * sc + (be[k] - m * sc);
            }
        }
        uint32_t hi[4], lo[4];
        #pragma unroll
        for (int j = 0; j < 4; j++) {
            __nv_bfloat162 h = __floats2bfloat162_rn(f[j * 2], f[j * 2 + 1]);
            __nv_bfloat162 l = __floats2bfloat162_rn(f[j * 2] - __bfloat162float(h.x),
                                                     f[j * 2 + 1] - __bfloat162float(h.y));
            hi[j] = *(uint32_t*)&h; lo[j] = *(uint32_t*)&l;
        }
        uint32_t sw = swz(sRow, sQuad * 16);
        *(uint4*)(sA[buf][0] + sw) = make_uint4(hi[0], hi[1], hi[2], hi[3]);
        *(uint4*)(sA[buf][1] + sw) = make_uint4(lo[0], lo[1], lo[2], lo[3]);
    };
    auto cpB = [&](int ch, int buf) {
        int koff = ch * 32;
        size_t g = (size_t)(n0 + bRow) * Kfull + koff + bHalf * 16;
        cp16(uB[buf][0] + swz(bRow, bHalf * 32), Bh + g);
        cp16(uB[buf][0] + swz(bRow, bHalf * 32 + 16), Bh + g + 8);
        cp16(uB[buf][1] + swz(bRow, bHalf * 32), Bl + g);
        cp16(uB[buf][1] + swz(bRow, bHalf * 32 + 16), Bl + g + 8);
    };

    float d[8][4];
    #pragma unroll
    for (int a = 0; a < 8; a++)
        #pragma unroll
        for (int b = 0; b < 4; b++) d[a][b] = 0.f;

    ldgA(0); cpB(0, 0); CP_COMMIT();
    cvtA(0, 0);
    CP_WAIT0();
    __syncthreads();

    int mid = lane >> 3, r8 = lane & 7;
    int buf = 0;
    for (int ch = 0; ch < nChunks; ch++) {
        bool more = ch + 1 < nChunks;
        if (more) { ldgA(ch + 1); cpB(ch + 1, buf ^ 1); CP_COMMIT(); }

        #pragma unroll
        for (int kk = 0; kk < 2; kk++) {
            uint32_t ah[4], al[4];
            {
                int arow = wm * 16 + (mid & 1) * 8 + r8;
                uint32_t kb = (uint32_t)(kk * 32 + (mid >> 1) * 16);
                uint32_t sw = swz(arow, kb);
                ldsm4(ah, uA[buf][0] + sw);
                ldsm4(al, uA[buf][1] + sw);
            }
            uint32_t bh[8][2], bl[8][2];
            #pragma unroll
            for (int ntp = 0; ntp < 4; ntp++) {
                int brow = wn * 64 + ntp * 16 + (mid >> 1) * 8 + r8;
                uint32_t kb = (uint32_t)(kk * 32 + (mid & 1) * 16);
                uint32_t sw = swz(brow, kb);
                uint32_t tmp[4];
                ldsm4(tmp, uB[buf][0] + sw);
                bh[ntp * 2 + 0][0] = tmp[0]; bh[ntp * 2 + 0][1] = tmp[1];
                bh[ntp * 2 + 1][0] = tmp[2]; bh[ntp * 2 + 1][1] = tmp[3];
                ldsm4(tmp, uB[buf][1] + sw);
                bl[ntp * 2 + 0][0] = tmp[0]; bl[ntp * 2 + 0][1] = tmp[1];
                bl[ntp * 2 + 1][0] = tmp[2]; bl[ntp * 2 + 1][1] = tmp[3];
            }
            #pragma unroll
            for (int nt = 0; nt < 8; nt++) {
                mma16816(d[nt], ah, bh[nt]);
                mma16816(d[nt], ah, bl[nt]);
                mma16816(d[nt], al, bh[nt]);
            }
        }

        if (more) { cvtA(ch + 1, buf ^ 1); CP_WAIT0(); }
        __syncthreads();
        buf ^= 1;
    }

    // ---- epilogue ----
    int rq = lane >> 2, cq = (lane & 3) * 2;
    int grow0 = m0 + wm * 16 + rq;
    if (w2) {
        float p0 = 0.f, p1 = 0.f;
        #pragma unroll
        for (int nt = 0; nt < 8; nt++) {
            int gcol = n0 + wn * 64 + nt * 8 + cq;
            float2 bv = *(const float2*)(bias + gcol);
            float o0x = fmaxf(d[nt][0] + bv.x, 0.f), o0y = fmaxf(d[nt][1] + bv.y, 0.f);
            float o1x = fmaxf(d[nt][2] + bv.x, 0.f), o1y = fmaxf(d[nt][3] + bv.y, 0.f);
            float2 wv = *(const float2*)(w2 + gcol);
            p0 += o0x * wv.x + o0y * wv.y;
            p1 += o1x * wv.x + o1y * wv.y;
        }
        p0 += __shfl_xor_sync(0xffffffffu, p0, 1);
        p0 += __shfl_xor_sync(0xffffffffu, p0, 2);
        p1 += __shfl_xor_sync(0xffffffffu, p1, 1);
        p1 += __shfl_xor_sync(0xffffffffu, p1, 2);
        if ((lane & 3) == 0) {
            if (grow0 < M)     atomicAdd(&outAcc[grow0], p0);
            if (grow0 + 8 < M) atomicAdd(&outAcc[grow0 + 8], p1);
        }
    } else {
        #pragma unroll
        for (int nt = 0; nt < 8; nt++) {
            int gcol = n0 + wn * 64 + nt * 8 + cq;
            float2 bv = make_float2(0.f, 0.f);
            if (bias) bv = *(const float2*)(bias + gcol);
            float2 o0 = make_float2(d[nt][0] + bv.x, d[nt][1] + bv.y);
            float2 o1 = make_float2(d[nt][2] + bv.x, d[nt][3] + bv.y);
            if (doRelu) {
                o0.x = fmaxf(o0.x, 0.f); o0.y = fmaxf(o0.y, 0.f);
                o1.x = fmaxf(o1.x, 0.f); o1.y = fmaxf(o1.y, 0.f);
            }
            if (grow0 < M)     *(float2*)(C + (size_t)grow0 * Ncols + gcol) = o0;
            if (grow0 + 8 < M) *(float2*)(C + (size_t)(grow0 + 8) * Ncols + gcol) = o1;
        }
    }
}

// ---------------- edge infra ----------------
__global__ void k_count(const int* __restrict__ col, const float* __restrict__ ew) {
    int e = blockIdx.x * blockDim.x + threadIdx.x;
    if (e >= N_EDGES) return;
    int c = col[e];
    atomicAdd(&g_cnt[c], 1);
    atomicAdd(&g_deg[c], ew[e]);
}

__global__ void k_scan() {   // shuffle-based scan, 2 barriers
    __shared__ int wsum[32];
    const int PER = 10;
    int t = threadIdx.x;
    int lane = t & 31, warp = t >> 5;
    int base = t * PER;
    int loc[PER];
    int s = 0;
    #pragma unroll
    for (int p = 0; p < PER; p++) {
        int idx = base + p;
        int v = (idx < N_NODES) ? g_cnt[idx] : 0;
        loc[p] = s; s += v;
    }
    // warp-inclusive scan of per-thread sums
    int inc = s;
    #pragma unroll
    for (int off = 1; off < 32; off <<= 1) {
        int n = __shfl_up_sync(0xffffffffu, inc, off);
        if (lane >= off) inc += n;
    }
    if (lane == 31) wsum[warp] = inc;
    __syncthreads();
    if (warp == 0) {
        int w = wsum[lane];
        #pragma unroll
        for (int off = 1; off < 32; off <<= 1) {
            int n = __shfl_up_sync(0xffffffffu, w, off);
            if (lane >= off) w += n;
        }
        wsum[lane] = w;
    }
    __syncthreads();
    int excl = (warp ? wsum[warp - 1] : 0) + inc - s;
    #pragma unroll
    for (int p = 0; p < PER; p++) {
        int idx = base + p;
        if (idx < N_NODES) g_offs[idx] = excl + loc[p];
    }
    if (t == 1023) g_offs[N_NODES] = excl + s;
}

__global__ void k_fill(const int* __restrict__ row, const int* __restrict__ col,
                       const float* __restrict__ ew) {
    int e = blockIdx.x * blockDim.x + threadIdx.x;
    if (e < N_NODES) g_deg[e] = rsqrtf(g_deg[e] + 1.0f);
    if (e >= N_EDGES) return;
    int c = col[e];
    int p = atomicAdd(&g_cur[c], 1);
    int dst = g_offs[c] + p;
    g_srow[dst] = row[e];
    g_sew[dst]  = ew[e];
}

// ---------------- GCN aggregation + fused BN stats ----------------
__global__ void k_gcn(const float* __restrict__ hlin, const float* __restrict__ bias,
                      float* __restrict__ pre, float* __restrict__ stats)
{
    __shared__ float sS[HID], sQ[HID];
    int t = threadIdx.x;
    if (t < HID) { sS[t] = 0.f; sQ[t] = 0.f; }
    __syncthreads();
    int warp = t >> 5, lane = t & 31;
    int i = blockIdx.x * 8 + warp;
    if (i < N_NODES) {
        float di = g_deg[i];
        int s = g_offs[i], epnd = g_offs[i + 1];
        float4 acc = make_float4(0.f, 0.f, 0.f, 0.f);
        for (int idx = s; idx < epnd; idx++) {
            int r = g_srow[idx];
            float nrm = g_deg[r] * g_sew[idx] * di;
            float4 v = *(const float4*)(hlin + (size_t)r * HID + lane * 4);
            acc.x += nrm * v.x; acc.y += nrm * v.y;
            acc.z += nrm * v.z; acc.w += nrm * v.w;
        }
        float4 hs = *(const float4*)(hlin + (size_t)i * HID + lane * 4);
        float sl = di * di;
        float4 b4 = *(const float4*)(bias + lane * 4);
        float4 o;
        o.x = fmaxf(acc.x + hs.x * sl + b4.x, 0.f);
        o.y = fmaxf(acc.y + hs.y * sl + b4.y, 0.f);
        o.z = fmaxf(acc.z + hs.z * sl + b4.z, 0.f);
        o.w = fmaxf(acc.w + hs.w * sl + b4.w, 0.f);
        *(float4*)(pre + (size_t)i * HID + lane * 4) = o;
        int f = lane * 4;
        atomicAdd(&sS[f + 0], o.x); atomicAdd(&sQ[f + 0], o.x * o.x);
        atomicAdd(&sS[f + 1], o.y); atomicAdd(&sQ[f + 1], o.y * o.y);
        atomicAdd(&sS[f + 2], o.z); atomicAdd(&sQ[f + 2], o.z * o.z);
        atomicAdd(&sS[f + 3], o.w); atomicAdd(&sQ[f + 3], o.w * o.w);
    }
    __syncthreads();
    if (t < HID) {
        atomicAdd(&stats[t], sS[t]);
        atomicAdd(&stats[HID + t], sQ[t]);
    }
}

// ---------------- level-0 assignment + fused xp0 ----------------
__global__ void k_assign0(const float* __restrict__ w, const float* __restrict__ bias,
                          const float* __restrict__ gum) {
    __shared__ float sW[NC0][HID];
    __shared__ float sAcc[NC0][HID];
    int t = threadIdx.x;
    for (int i = t; i < HID * NC0; i += 256) {
        int k = i / NC0, c = i % NC0;
        sW[c][k] = w[i];
        ((float*)sAcc)[i] = 0.f;
    }
    __syncthreads();
    int warp = t >> 5, lane = t & 31;
    for (int n = blockIdx.x * 8 + warp; n < N_NODES; n += gridDim.x * 8) {
        float4 xv = *(const float4*)(g_bottom + (size_t)n * HID + lane * 4);
        float best = -1e30f; int bi = 0;
        #pragma unroll
        for (int c = 0; c < NC0; c++) {
            float4 wv = *(float4*)&sW[c][lane * 4];
            float p = xv.x * wv.x + xv.y * wv.y + xv.z * wv.z + xv.w * wv.w;
            #pragma unroll
            for (int off = 16; off > 0; off >>= 1)
                p += __shfl_xor_sync(0xffffffffu, p, off);
            p += bias[c] + gum[(size_t)n * NC0 + c];
            if (p > best) { best = p; bi = c; }
        }
        if (lane == 0) g_c0[n] = bi;
        int f = lane * 4;
        atomicAdd(&sAcc[bi][f + 0], xv.x);
        atomicAdd(&sAcc[bi][f + 1], xv.y);
        atomicAdd(&sAcc[bi][f + 2], xv.z);
        atomicAdd(&sAcc[bi][f + 3], xv.w);
    }
    __syncthreads();
    for (int i = t; i < NC0 * HID; i += 256)
        atomicAdd(&g_xp0[i], ((float*)sAcc)[i]);
}

__global__ void k_A0(const int* __restrict__ row, const int* __restrict__ col,
                     const float* __restrict__ ew) {
    __shared__ float sA[NC0 * NC0];
    int t = threadIdx.x;
    if (t < NC0 * NC0) sA[t] = 0.f;
    __syncthreads();
    for (int e = blockIdx.x * blockDim.x + t; e < N_EDGES; e += gridDim.x * blockDim.x)
        atomicAdd(&sA[g_c0[row[e]] * NC0 + g_c0[col[e]]], ew[e]);
    __syncthreads();
    if (t < NC0 * NC0) atomicAdd(&g_A0[t], sA[t]);
}

// ---------------- tiny hierarchical pooling math ----------------
__device__ __forceinline__ float blockReduce128(float v, float* red) {
    int t = threadIdx.x;
    red[t] = v; __syncthreads();
    #pragma unroll
    for (int off = 64; off > 0; off >>= 1) {
        if (t < off) red[t] += red[t + off];
        __syncthreads();
    }
    float r = red[0]; __syncthreads();
    return r;
}

__global__ void k_levels(const float* __restrict__ me0_w, const float* __restrict__ me0_b,
                         const float* __restrict__ ml1_w, const float* __restrict__ ml1_b,
                         const float* __restrict__ gum1,
                         const float* __restrict__ me1_w, const float* __restrict__ me1_b)
{
    __shared__ float sA0[NC0 * NC0];
    __shared__ float sXp[NC0][HID];
    __shared__ float sM[NC0][HID];
    __shared__ float sL0[NC0][HID];
    __shared__ float sXp1[NC1][HID];
    __shared__ float sM1[NC1][HID];
    __shared__ float red[HID];
    __shared__ float sZ[NC0][NC1];
    __shared__ float sA1[NC1 * NC1];
    __shared__ int   sC1[NC0];
    int t = threadIdx.x;

    float a = (t < NC0 * NC0) ? g_A0[t] : 0.f;
    float S0 = blockReduce128(a, red);
    if (t < NC0 * NC0) sA0[t] = a / S0;
    __syncthreads();

    for (int c = 0; c < NC0; c++) {
        float v = g_xp0[c * HID + t];
        float nsq = blockReduce128(v * v, red);
        float nrm = sqrtf(nsq);
        sXp[c][t] = v / fmaxf(nrm, 1e-12f);
    }
    __syncthreads();

    for (int c = 0; c < NC0; c++) {
        float s = 0.f;
        #pragma unroll
        for (int k = 0; k < NC0; k++) s += sA0[c * NC0 + k] * sXp[k][t];
        sM[c][t] = s;
    }
    __syncthreads();

    {
        float acc[NC0];
        #pragma unroll
        for (int c = 0; c < NC0; c++) acc[c] = me0_b[t];
        for (int k = 0; k < HID; k++) {
            float w = me0_w[k * HID + t];
            #pragma unroll
            for (int c = 0; c < NC0; c++) acc[c] += sM[c][k] * w;
        }
        #pragma unroll
        for (int c = 0; c < NC0; c++) {
            float v = tanhf(acc[c]);
            sL0[c][t] = v;
            g_latent0[c * HID + t] = v;
        }
    }
    __syncthreads();

    if (t < NC0 * NC1) {
        int k = t / NC1, c = t % NC1;
        float s = ml1_b[c] + gum1[k * NC1 + c];
        for (int j = 0; j < HID; j++) s += sL0[k][j] * ml1_w[j * NC1 + c];
        sZ[k][c] = s;
    }
    __syncthreads();
    if (t < NC0) {
        float best = sZ[t][0]; int bi = 0;
        #pragma unroll
        for (int c = 1; c < NC1; c++)
            if (sZ[t][c] > best) { best = sZ[t][c]; bi = c; }
        sC1[t] = bi;
        g_c1[t] = bi;
    }
    __syncthreads();

    for (int c = 0; c < NC1; c++) {
        float v = 0.f;
        #pragma unroll
        for (int k = 0; k < NC0; k++)
            if (sC1[k] == c) v += sL0[k][t];
        float nsq = blockReduce128(v * v, red);
        float nrm = sqrtf(nsq);
        sXp1[c][t] = v / fmaxf(nrm, 1e-12f);
    }
    __syncthreads();

    if (t < NC1 * NC1) {
        int aa = t / NC1, bb = t % NC1;
        float s = 0.f;
        for (int k = 0; k < NC0; k++)
            for (int l = 0; l < NC0; l++)
                if (sC1[k] == aa && sC1[l] == bb) s += sA0[k * NC0 + l];
        sA1[t] = s;
    }
    __syncthreads();
    float a1v = (t < NC1 * NC1) ? sA1[t] : 0.f;
    float S1 = blockReduce128(a1v, red);
    if (t < NC1 * NC1) sA1[t] = a1v / S1;
    __syncthreads();

    for (int c = 0; c < NC1; c++) {
        float s = 0.f;
        #pragma unroll
        for (int k = 0; k < NC1; k++) s += sA1[c * NC1 + k] * sXp1[k][t];
        sM1[c][t] = s;
    }
    __syncthreads();
    {
        float acc[NC1];
        #pragma unroll
        for (int c = 0; c < NC1; c++) acc[c] = me1_b[t];
        for (int k = 0; k < HID; k++) {
            float w = me1_w[k * HID + t];
            #pragma unroll
            for (int c = 0; c < NC1; c++) acc[c] += sM1[c][k] * w;
        }
        #pragma unroll
        for (int c = 0; c < NC1; c++) g_latent1[c * HID + t] = tanhf(acc[c]);
    }
}

// ---------------- final bias + relu ----------------
__global__ void k_fin(float* __restrict__ out, const float* __restrict__ b) {
    int i = blockIdx.x * blockDim.x + threadIdx.x;
    if (i < N_NODES) out[i] = fmaxf(out[i] + b[0], 0.f);
}

// ---------------- host ----------------
extern "C" void kernel_launch(void* const* d_in, const int* in_sizes, int n_in,
                              void* d_out, int out_size)
{
    const float* x       = (const float*)d_in[0];
    const float* ew      = (const float*)d_in[1];
    const float* gum0    = (const float*)d_in[2];
    const float* gum1    = (const float*)d_in[3];
    const float* conv1_w = (const float*)d_in[4];
    const float* conv1_b = (const float*)d_in[5];
    const float* conv2_w = (const float*)d_in[6];
    const float* conv2_b = (const float*)d_in[7];
    const float* bn1_g   = (const float*)d_in[8];
    const float* bn1_b   = (const float*)d_in[9];
    const float* bn2_g   = (const float*)d_in[10];
    const float* bn2_b   = (const float*)d_in[11];
    const float* enc1_w  = (const float*)d_in[12];
    const float* enc1_b  = (const float*)d_in[13];
    const float* enc2_w  = (const float*)d_in[14];
    const float* enc2_b  = (const float*)d_in[15];
    const float* ml0_w   = (const float*)d_in[16];
    const float* ml0_b   = (const float*)d_in[17];
    const float* ml1_w   = (const float*)d_in[18];
    const float* ml1_b   = (const float*)d_in[19];
    const float* me0_w   = (const float*)d_in[20];
    const float* me0_b   = (const float*)d_in[21];
    const float* me1_w   = (const float*)d_in[22];
    const float* me1_b   = (const float*)d_in[23];
    const float* fc1_w   = (const float*)d_in[24];
    const float* fc1_b   = (const float*)d_in[25];
    const float* fc2_w   = (const float*)d_in[26];
    const float* fc2_b   = (const float*)d_in[27];
    const int*   ei      = (const int*)d_in[28];
    const int* row = ei;
    const int* col = ei + N_EDGES;
    float* out = (float*)d_out;

    float *p_hlin, *p_pre1, *p_pre2, *p_e1, *p_bottom;
    float *p_stats1, *p_stats2, *p_lat0, *p_lat1;
    __nv_bfloat16 *p_wh, *p_wl;
    cudaGetSymbolAddress((void**)&p_hlin,   g_hlin);
    cudaGetSymbolAddress((void**)&p_pre1,   g_pre1);
    cudaGetSymbolAddress((void**)&p_pre2,   g_pre2);
    cudaGetSymbolAddress((void**)&p_e1,     g_e1);
    cudaGetSymbolAddress((void**)&p_bottom, g_bottom);
    cudaGetSymbolAddress((void**)&p_stats1, g_stats1);
    cudaGetSymbolAddress((void**)&p_stats2, g_stats2);
    cudaGetSymbolAddress((void**)&p_lat0,   g_latent0);
    cudaGetSymbolAddress((void**)&p_lat1,   g_latent1);
    cudaGetSymbolAddress((void**)&p_wh,     g_wh);
    cudaGetSymbolAddress((void**)&p_wl,     g_wl);

    const int GB = (N_NODES + 63) / 64;   // 157
    dim3 g1(GB, 1), g4(GB, 4);

    // #1 fused weight prep + zeroing
    k_wz<<<(W_TOTAL + 255) / 256, 256>>>(conv1_w, conv2_w, enc1_w, enc2_w, fc1_w, out);
    // #2, #3 edge histogram + scan
    k_count<<<(N_EDGES + 255) / 256, 256>>>(col, ew);
    k_scan<<<1, 1024>>>();
    // #4: conv1 GEMM (independent of CSR fill) — lands in the ncu profile slot
    tgemm<<<g1, 256>>>(x, nullptr, nullptr,
                       nullptr, nullptr, nullptr, nullptr, nullptr, nullptr,
                       nullptr, nullptr, nullptr,
                       p_wh + WO_CONV1, p_wl + WO_CONV1, nullptr, p_hlin,
                       nullptr, nullptr, N_NODES, 1, 128, 0, 0);
    // #5 CSR fill (+ dinv)
    k_fill<<<(N_EDGES + 255) / 256, 256>>>(row, col, ew);
    // conv1 aggregation
    k_gcn<<<1250, 256>>>(p_hlin, conv1_b, p_pre1, p_stats1);

    // conv2
    tgemm<<<g1, 256>>>(p_pre1, nullptr, nullptr,
                       p_stats1, bn1_g, bn1_b, nullptr, nullptr, nullptr,
                       nullptr, nullptr, nullptr,
                       p_wh + WO_CONV2, p_wl + WO_CONV2, nullptr, p_hlin,
                       nullptr, nullptr, N_NODES, 1, 128, 0, 0);
    k_gcn<<<1250, 256>>>(p_hlin, conv2_b, p_pre2, p_stats2);

    // enc1 / enc2
    tgemm<<<g1, 256>>>(x, p_pre1, p_pre2,
                       nullptr, nullptr, nullptr,
                       p_stats1, bn1_g, bn1_b,
                       p_stats2, bn2_g, bn2_b,
                       p_wh + WO_ENC1, p_wl + WO_ENC1, enc1_b, p_e1,
                       nullptr, nullptr, N_NODES, 3, 128, 1, 0);
    tgemm<<<g1, 256>>>(p_e1, nullptr, nullptr,
                       nullptr, nullptr, nullptr, nullptr, nullptr, nullptr,
                       nullptr, nullptr, nullptr,
                       p_wh + WO_ENC2, p_wl + WO_ENC2, enc2_b, p_bottom,
                       nullptr, nullptr, N_NODES, 1, 128, 1, 0);

    // hierarchical pooling
    k_assign0<<<80, 256>>>(ml0_w, ml0_b, gum0);
    k_A0<<<120, 256>>>(row, col, ew);
    k_levels<<<1, 128>>>(me0_w, me0_b, ml1_w, ml1_b, gum1, me1_w, me1_b);

    // fc1 with fused fc2 partial-dot epilogue
    tgemm<<<g4, 256>>>(p_bottom, p_lat0, p_lat1,
                       nullptr, nullptr, nullptr, nullptr, nullptr, nullptr,
                       nullptr, nullptr, nullptr,
                       p_wh + WO_FC1, p_wl + WO_FC1, fc1_b, nullptr,
                       fc2_w, out, N_NODES, 3, 512, 1, 1);
    k_fin<<<(N_NODES + 255) / 256, 256>>>(out, fc2_b);
}

// round 8
// speedup vs baseline: 2.3692x; 1.0076x over previous
#include <cuda_runtime.h>
#include <cuda_bf16.h>
#include <stdint.h>
#include <math.h>

#define N_NODES 10000
#define N_EDGES 320000
#define HID 128
#define NC0 10
#define NC1 5

// ---------------- device scratch ----------------
__device__ float g_deg[N_NODES];
__device__ int   g_cnt[N_NODES];
__device__ int   g_cur[N_NODES];
__device__ int   g_offs[N_NODES + 1];
__device__ int   g_srow[N_EDGES];
__device__ float g_sew[N_EDGES];
__device__ float g_hlin[N_NODES * HID];
__device__ float g_pre1[N_NODES * HID];
__device__ float g_pre2[N_NODES * HID];
__device__ float g_e1[N_NODES * HID];
__device__ float g_bottom[N_NODES * HID];
__device__ float g_stats1[2 * HID];
__device__ float g_stats2[2 * HID];
__device__ int   g_c0[N_NODES];
__device__ int   g_c1[NC0];
__device__ float g_xp0[NC0 * HID];
__device__ float g_A0[NC0 * NC0];
__device__ float g_latent0[NC0 * HID];
__device__ float g_latent1[NC1 * HID];

// pre-converted transposed weights [N][K] bf16 hi/lo
#define WO_CONV1 0
#define WO_CONV2 16384
#define WO_ENC1  32768
#define WO_ENC2  81920
#define WO_FC1   98304
#define W_TOTAL  294912
__device__ __align__(16) __nv_bfloat16 g_wh[W_TOTAL];
__device__ __align__(16) __nv_bfloat16 g_wl[W_TOTAL];

// ---------------- PTX wrappers ----------------
__device__ __forceinline__ uint32_t smem_u32(const void* p) {
    uint32_t a;
    asm("{ .reg .u64 t; cvta.to.shared.u64 t, %1; cvt.u32.u64 %0, t; }" : "=r"(a) : "l"(p));
    return a;
}
__device__ __forceinline__ void ldsm4(uint32_t r[4], uint32_t addr) {
    asm volatile("ldmatrix.sync.aligned.m8n8.x4.shared.b16 {%0,%1,%2,%3}, [%4];"
        : "=r"(r[0]), "=r"(r[1]), "=r"(r[2]), "=r"(r[3]) : "r"(addr));
}
__device__ __forceinline__ void mma16816(float d[4], const uint32_t a[4], const uint32_t b[2]) {
    asm volatile("mma.sync.aligned.m16n8k16.row.col.f32.bf16.bf16.f32 "
        "{%0,%1,%2,%3}, {%4,%5,%6,%7}, {%8,%9}, {%0,%1,%2,%3};"
        : "+f"(d[0]), "+f"(d[1]), "+f"(d[2]), "+f"(d[3])
        : "r"(a[0]), "r"(a[1]), "r"(a[2]), "r"(a[3]), "r"(b[0]), "r"(b[1]));
}
__device__ __forceinline__ void cp16(uint32_t d, const void* s) {
    asm volatile("cp.async.cg.shared.global [%0], [%1], 16;" :: "r"(d), "l"(s));
}
#define CP_COMMIT() asm volatile("cp.async.commit_group;" ::: "memory")
#define CP_WAIT0()  asm volatile("cp.async.wait_group 0;" ::: "memory")

// swizzled byte offset inside a [rows][32 bf16] tile (row stride 64B)
__device__ __forceinline__ uint32_t swz(int row, int kb) {
    int c = kb >> 4;
    int rem = kb & 15;
    int cp = c ^ ((row >> 1) & 3);
    return (uint32_t)(row * 64 + cp * 16 + rem);
}

// ---------------- fused weight prep + state zeroing ----------------
__global__ void k_wz(const float* __restrict__ w1, const float* __restrict__ w2,
                     const float* __restrict__ we1, const float* __restrict__ we2,
                     const float* __restrict__ wf1, float* __restrict__ out) {
    int i = blockIdx.x * blockDim.x + threadIdx.x;
    if (i < N_NODES) { g_deg[i] = 0.f; g_cnt[i] = 0; g_cur[i] = 0; out[i] = 0.f; }
    if (i < 2 * HID) { g_stats1[i] = 0.f; g_stats2[i] = 0.f; }
    if (i < NC0 * HID) g_xp0[i] = 0.f;
    if (i < NC0 * NC0) g_A0[i] = 0.f;
    if (i >= W_TOTAL) return;
    const float* w; int K, Nn; int d = i;
    if (d < 16384)       { w = w1;  K = 128; Nn = 128; }
    else if (d < 32768)  { w = w2;  K = 128; Nn = 128; d -= 16384; }
    else if (d < 81920)  { w = we1; K = 384; Nn = 128; d -= 32768; }
    else if (d < 98304)  { w = we2; K = 128; Nn = 128; d -= 81920; }
    else                 { w = wf1; K = 384; Nn = 512; d -= 98304; }
    int n = d / K, k = d % K;
    float v = w[(size_t)k * Nn + n];
    __nv_bfloat16 h = __float2bfloat16(v);
    float l = v - __bfloat162float(h);
    g_wh[i] = h;
    g_wl[i] = __float2bfloat16(l);
}

// ---------------- bf16x3 tensor-core GEMM, 64x64 tile, double-buffered ----------------
__global__ __launch_bounds__(256, 3)
void tgemm(const float* __restrict__ A0, const float* __restrict__ A1, const float* __restrict__ A2,
           const float* __restrict__ st0, const float* __restrict__ ga0, const float* __restrict__ be0,
           const float* __restrict__ st1, const float* __restrict__ ga1, const float* __restrict__ be1,
           const float* __restrict__ st2, const float* __restrict__ ga2, const float* __restrict__ be2,
           const __nv_bfloat16* __restrict__ Bh, const __nv_bfloat16* __restrict__ Bl,
           const float* __restrict__ bias, float* __restrict__ C,
           const float* __restrict__ w2, float* __restrict__ outAcc,
           int M, int nseg, int Ncols, int doRelu, int idxmode)
{
    __shared__ __align__(16) char sA[2][2][4096];   // [buf][hi/lo][64 x 64B]
    __shared__ __align__(16) char sB[2][2][4096];   // [buf][hi/lo][64 x 64B]

    int t = threadIdx.x;
    int wid = t >> 5, lane = t & 31;
    int wm = wid >> 1, wn = wid & 1;            // 4 x 2 warps, each 16 x 32
    int m0 = blockIdx.x * 64, n0 = blockIdx.y * 64;

    int sRow = t >> 2, sQuad = t & 3;
    int gm = m0 + sRow;
    bool mOK = gm < M;
    int gi = mOK ? gm : 0;
    int i1 = gi, i2 = gi;
    if (idxmode && mOK) { i1 = g_c0[gi]; i2 = g_c1[i1]; }
    const float* rp[3];
    rp[0] = A0 ? A0 + (size_t)gi * 128 : (const float*)0;
    rp[1] = A1 ? A1 + (size_t)i1 * 128 : (const float*)0;
    rp[2] = A2 ? A2 + (size_t)i2 * 128 : (const float*)0;
    const float* stp[3] = { st0, st1, st2 };
    const float* gap[3] = { ga0, ga1, ga2 };
    const float* bep[3] = { be0, be1, be2 };

    int Kfull = nseg * 128;
    int nChunks = nseg * 4;
    const float invN = 1.0f / (float)N_NODES;

    uint32_t uA[2][2], uB[2][2];
    #pragma unroll
    for (int b = 0; b < 2; b++) {
        uA[b][0] = smem_u32(sA[b][0]); uA[b][1] = smem_u32(sA[b][1]);
        uB[b][0] = smem_u32(sB[b][0]); uB[b][1] = smem_u32(sB[b][1]);
    }

    float4 aPre[2];
    auto ldgA = [&](int ch) {
        int koff = ch * 32;
        int seg = koff >> 7;
        int kin = (koff & 127) + sQuad * 8;
        const float* ap = rp[seg] + kin;
        aPre[0] = mOK ? *(const float4*)(ap + 0) : make_float4(0.f, 0.f, 0.f, 0.f);
        aPre[1] = mOK ? *(const float4*)(ap + 4) : make_float4(0.f, 0.f, 0.f, 0.f);
    };
    auto cvtA = [&](int ch, int buf) {
        int koff = ch * 32;
        int seg = koff >> 7;
        int kin = (koff & 127) + sQuad * 8;
        float f[8] = { aPre[0].x, aPre[0].y, aPre[0].z, aPre[0].w,
                       aPre[1].x, aPre[1].y, aPre[1].z, aPre[1].w };
        if (stp[seg]) {
            const float* st = stp[seg];
            const float* ga = gap[seg];
            const float* be = bep[seg];
            #pragma unroll
            for (int j = 0; j < 8; j++) {
                int k = kin + j;
                float m = st[k] * invN;
                float var = st[HID + k] * invN - m * m;
                float sc = ga[k] * rsqrtf(var + 1e-5f);
                f[j] = f[j] * sc + (be[k] - m * sc);
            }
        }
        uint32_t hi[4], lo[4];
        #pragma unroll
        for (int j = 0; j < 4; j++) {
            __nv_bfloat162 h = __floats2bfloat162_rn(f[j * 2], f[j * 2 + 1]);
            __nv_bfloat162 l = __floats2bfloat162_rn(f[j * 2] - __bfloat162float(h.x),
                                                     f[j * 2 + 1] - __bfloat162float(h.y));
            hi[j] = *(uint32_t*)&h; lo[j] = *(uint32_t*)&l;
        }
        uint32_t sw = swz(sRow, sQuad * 16);
        *(uint4*)(sA[buf][0] + sw) = make_uint4(hi[0], hi[1], hi[2], hi[3]);
        *(uint4*)(sA[buf][1] + sw) = make_uint4(lo[0], lo[1], lo[2], lo[3]);
    };
    auto cpB = [&](int ch, int buf) {
        int koff = ch * 32;
        size_t g = (size_t)(n0 + sRow) * Kfull + koff + sQuad * 8;
        uint32_t sw = swz(sRow, sQuad * 16);
        cp16(uB[buf][0] + sw, Bh + g);
        cp16(uB[buf][1] + sw, Bl + g);
    };

    float d[4][4];
    #pragma unroll
    for (int a = 0; a < 4; a++)
        #pragma unroll
        for (int b = 0; b < 4; b++) d[a][b] = 0.f;

    ldgA(0); cpB(0, 0); CP_COMMIT();
    cvtA(0, 0);
    CP_WAIT0();
    __syncthreads();

    int mid = lane >> 3, r8 = lane & 7;
    int buf = 0;
    for (int ch = 0; ch < nChunks; ch++) {
        bool more = ch + 1 < nChunks;
        if (more) { ldgA(ch + 1); cpB(ch + 1, buf ^ 1); CP_COMMIT(); }

        #pragma unroll
        for (int kk = 0; kk < 2; kk++) {
            uint32_t ah[4], al[4];
            {
                int arow = wm * 16 + (mid & 1) * 8 + r8;
                uint32_t kb = (uint32_t)(kk * 32 + (mid >> 1) * 16);
                uint32_t sw = swz(arow, kb);
                ldsm4(ah, uA[buf][0] + sw);
                ldsm4(al, uA[buf][1] + sw);
            }
            uint32_t bh[4][2], bl[4][2];
            #pragma unroll
            for (int ntp = 0; ntp < 2; ntp++) {
                int brow = wn * 32 + ntp * 16 + (mid >> 1) * 8 + r8;
                uint32_t kb = (uint32_t)(kk * 32 + (mid & 1) * 16);
                uint32_t sw = swz(brow, kb);
                uint32_t tmp[4];
                ldsm4(tmp, uB[buf][0] + sw);
                bh[ntp * 2 + 0][0] = tmp[0]; bh[ntp * 2 + 0][1] = tmp[1];
                bh[ntp * 2 + 1][0] = tmp[2]; bh[ntp * 2 + 1][1] = tmp[3];
                ldsm4(tmp, uB[buf][1] + sw);
                bl[ntp * 2 + 0][0] = tmp[0]; bl[ntp * 2 + 0][1] = tmp[1];
                bl[ntp * 2 + 1][0] = tmp[2]; bl[ntp * 2 + 1][1] = tmp[3];
            }
            #pragma unroll
            for (int nt = 0; nt < 4; nt++) {
                mma16816(d[nt], ah, bh[nt]);
                mma16816(d[nt], ah, bl[nt]);
                mma16816(d[nt], al, bh[nt]);
            }
        }

        if (more) { cvtA(ch + 1, buf ^ 1); CP_WAIT0(); }
        __syncthreads();
        buf ^= 1;
    }

    // ---- epilogue ----
    int rq = lane >> 2, cq = (lane & 3) * 2;
    int grow0 = m0 + wm * 16 + rq;
    if (w2) {
        float p0 = 0.f, p1 = 0.f;
        #pragma unroll
        for (int nt = 0; nt < 4; nt++) {
            int gcol = n0 + wn * 32 + nt * 8 + cq;
            float2 bv = *(const float2*)(bias + gcol);
            float o0x = fmaxf(d[nt][0] + bv.x, 0.f), o0y = fmaxf(d[nt][1] + bv.y, 0.f);
            float o1x = fmaxf(d[nt][2] + bv.x, 0.f), o1y = fmaxf(d[nt][3] + bv.y, 0.f);
            float2 wv = *(const float2*)(w2 + gcol);
            p0 += o0x * wv.x + o0y * wv.y;
            p1 += o1x * wv.x + o1y * wv.y;
        }
        p0 += __shfl_xor_sync(0xffffffffu, p0, 1);
        p0 += __shfl_xor_sync(0xffffffffu, p0, 2);
        p1 += __shfl_xor_sync(0xffffffffu, p1, 1);
        p1 += __shfl_xor_sync(0xffffffffu, p1, 2);
        if ((lane & 3) == 0) {
            if (grow0 < M)     atomicAdd(&outAcc[grow0], p0);
            if (grow0 + 8 < M) atomicAdd(&outAcc[grow0 + 8], p1);
        }
    } else {
        #pragma unroll
        for (int nt = 0; nt < 4; nt++) {
            int gcol = n0 + wn * 32 + nt * 8 + cq;
            float2 bv = make_float2(0.f, 0.f);
            if (bias) bv = *(const float2*)(bias + gcol);
            float2 o0 = make_float2(d[nt][0] + bv.x, d[nt][1] + bv.y);
            float2 o1 = make_float2(d[nt][2] + bv.x, d[nt][3] + bv.y);
            if (doRelu) {
                o0.x = fmaxf(o0.x, 0.f); o0.y = fmaxf(o0.y, 0.f);
                o1.x = fmaxf(o1.x, 0.f); o1.y = fmaxf(o1.y, 0.f);
            }
            if (grow0 < M)     *(float2*)(C + (size_t)grow0 * Ncols + gcol) = o0;
            if (grow0 + 8 < M) *(float2*)(C + (size_t)(grow0 + 8) * Ncols + gcol) = o1;
        }
    }
}

// ---------------- edge infra ----------------
__global__ void k_count(const int* __restrict__ col, const float* __restrict__ ew) {
    int e = blockIdx.x * blockDim.x + threadIdx.x;
    if (e >= N_EDGES) return;
    int c = col[e];
    atomicAdd(&g_cnt[c], 1);
    atomicAdd(&g_deg[c], ew[e]);
}

__global__ void k_scan() {   // shuffle-based scan, 2 barriers
    __shared__ int wsum[32];
    const int PER = 10;
    int t = threadIdx.x;
    int lane = t & 31, warp = t >> 5;
    int base = t * PER;
    int loc[PER];
    int s = 0;
    #pragma unroll
    for (int p = 0; p < PER; p++) {
        int idx = base + p;
        int v = (idx < N_NODES) ? g_cnt[idx] : 0;
        loc[p] = s; s += v;
    }
    int inc = s;
    #pragma unroll
    for (int off = 1; off < 32; off <<= 1) {
        int n = __shfl_up_sync(0xffffffffu, inc, off);
        if (lane >= off) inc += n;
    }
    if (lane == 31) wsum[warp] = inc;
    __syncthreads();
    if (warp == 0) {
        int w = wsum[lane];
        #pragma unroll
        for (int off = 1; off < 32; off <<= 1) {
            int n = __shfl_up_sync(0xffffffffu, w, off);
            if (lane >= off) w += n;
        }
        wsum[lane] = w;
    }
    __syncthreads();
    int excl = (warp ? wsum[warp - 1] : 0) + inc - s;
    #pragma unroll
    for (int p = 0; p < PER; p++) {
        int idx = base + p;
        if (idx < N_NODES) g_offs[idx] = excl + loc[p];
    }
    if (t == 1023) g_offs[N_NODES] = excl + s;
}

__global__ void k_fill(const int* __restrict__ row, const int* __restrict__ col,
                       const float* __restrict__ ew) {
    int e = blockIdx.x * blockDim.x + threadIdx.x;
    if (e < N_NODES) g_deg[e] = rsqrtf(g_deg[e] + 1.0f);
    if (e >= N_EDGES) return;
    int c = col[e];
    int p = atomicAdd(&g_cur[c], 1);
    int dst = g_offs[c] + p;
    g_srow[dst] = row[e];
    g_sew[dst]  = ew[e];
}

// ---------------- GCN aggregation + fused BN stats ----------------
__global__ void k_gcn(const float* __restrict__ hlin, const float* __restrict__ bias,
                      float* __restrict__ pre, float* __restrict__ stats)
{
    __shared__ float sS[HID], sQ[HID];
    int t = threadIdx.x;
    if (t < HID) { sS[t] = 0.f; sQ[t] = 0.f; }
    __syncthreads();
    int warp = t >> 5, lane = t & 31;
    int i = blockIdx.x * 8 + warp;
    if (i < N_NODES) {
        float di = g_deg[i];
        int s = g_offs[i], epnd = g_offs[i + 1];
        float4 acc = make_float4(0.f, 0.f, 0.f, 0.f);
        for (int idx = s; idx < epnd; idx++) {
            int r = g_srow[idx];
            float nrm = g_deg[r] * g_sew[idx] * di;
            float4 v = *(const float4*)(hlin + (size_t)r * HID + lane * 4);
            acc.x += nrm * v.x; acc.y += nrm * v.y;
            acc.z += nrm * v.z; acc.w += nrm * v.w;
        }
        float4 hs = *(const float4*)(hlin + (size_t)i * HID + lane * 4);
        float sl = di * di;
        float4 b4 = *(const float4*)(bias + lane * 4);
        float4 o;
        o.x = fmaxf(acc.x + hs.x * sl + b4.x, 0.f);
        o.y = fmaxf(acc.y + hs.y * sl + b4.y, 0.f);
        o.z = fmaxf(acc.z + hs.z * sl + b4.z, 0.f);
        o.w = fmaxf(acc.w + hs.w * sl + b4.w, 0.f);
        *(float4*)(pre + (size_t)i * HID + lane * 4) = o;
        int f = lane * 4;
        atomicAdd(&sS[f + 0], o.x); atomicAdd(&sQ[f + 0], o.x * o.x);
        atomicAdd(&sS[f + 1], o.y); atomicAdd(&sQ[f + 1], o.y * o.y);
        atomicAdd(&sS[f + 2], o.z); atomicAdd(&sQ[f + 2], o.z * o.z);
        atomicAdd(&sS[f + 3], o.w); atomicAdd(&sQ[f + 3], o.w * o.w);
    }
    __syncthreads();
    if (t < HID) {
        atomicAdd(&stats[t], sS[t]);
        atomicAdd(&stats[HID + t], sQ[t]);
    }
}

// ---------------- level-0 assignment + fused xp0 ----------------
__global__ void k_assign0(const float* __restrict__ w, const float* __restrict__ bias,
                          const float* __restrict__ gum) {
    __shared__ float sW[NC0][HID];
    __shared__ float sAcc[NC0][HID];
    int t = threadIdx.x;
    for (int i = t; i < HID * NC0; i += 256) {
        int k = i / NC0, c = i % NC0;
        sW[c][k] = w[i];
        ((float*)sAcc)[i] = 0.f;
    }
    __syncthreads();
    int warp = t >> 5, lane = t & 31;
    for (int n = blockIdx.x * 8 + warp; n < N_NODES; n += gridDim.x * 8) {
        float4 xv = *(const float4*)(g_bottom + (size_t)n * HID + lane * 4);
        float best = -1e30f; int bi = 0;
        #pragma unroll
        for (int c = 0; c < NC0; c++) {
            float4 wv = *(float4*)&sW[c][lane * 4];
            float p = xv.x * wv.x + xv.y * wv.y + xv.z * wv.z + xv.w * wv.w;
            #pragma unroll
            for (int off = 16; off > 0; off >>= 1)
                p += __shfl_xor_sync(0xffffffffu, p, off);
            p += bias[c] + gum[(size_t)n * NC0 + c];
            if (p > best) { best = p; bi = c; }
        }
        if (lane == 0) g_c0[n] = bi;
        int f = lane * 4;
        atomicAdd(&sAcc[bi][f + 0], xv.x);
        atomicAdd(&sAcc[bi][f + 1], xv.y);
        atomicAdd(&sAcc[bi][f + 2], xv.z);
        atomicAdd(&sAcc[bi][f + 3], xv.w);
    }
    __syncthreads();
    for (int i = t; i < NC0 * HID; i += 256)
        atomicAdd(&g_xp0[i], ((float*)sAcc)[i]);
}

__global__ void k_A0(const int* __restrict__ row, const int* __restrict__ col,
                     const float* __restrict__ ew) {
    __shared__ float sA[NC0 * NC0];
    int t = threadIdx.x;
    if (t < NC0 * NC0) sA[t] = 0.f;
    __syncthreads();
    for (int e = blockIdx.x * blockDim.x + t; e < N_EDGES; e += gridDim.x * blockDim.x)
        atomicAdd(&sA[g_c0[row[e]] * NC0 + g_c0[col[e]]], ew[e]);
    __syncthreads();
    if (t < NC0 * NC0) atomicAdd(&g_A0[t], sA[t]);
}

// ---------------- tiny hierarchical pooling math ----------------
__device__ __forceinline__ float blockReduce128(float v, float* red) {
    int t = threadIdx.x;
    red[t] = v; __syncthreads();
    #pragma unroll
    for (int off = 64; off > 0; off >>= 1) {
        if (t < off) red[t] += red[t + off];
        __syncthreads();
    }
    float r = red[0]; __syncthreads();
    return r;
}

__global__ void k_levels(const float* __restrict__ me0_w, const float* __restrict__ me0_b,
                         const float* __restrict__ ml1_w, const float* __restrict__ ml1_b,
                         const float* __restrict__ gum1,
                         const float* __restrict__ me1_w, const float* __restrict__ me1_b)
{
    __shared__ float sA0[NC0 * NC0];
    __shared__ float sXp[NC0][HID];
    __shared__ float sM[NC0][HID];
    __shared__ float sL0[NC0][HID];
    __shared__ float sXp1[NC1][HID];
    __shared__ float sM1[NC1][HID];
    __shared__ float red[HID];
    __shared__ float sZ[NC0][NC1];
    __shared__ float sA1[NC1 * NC1];
    __shared__ int   sC1[NC0];
    int t = threadIdx.x;

    float a = (t < NC0 * NC0) ? g_A0[t] : 0.f;
    float S0 = blockReduce128(a, red);
    if (t < NC0 * NC0) sA0[t] = a / S0;
    __syncthreads();

    for (int c = 0; c < NC0; c++) {
        float v = g_xp0[c * HID + t];
        float nsq = blockReduce128(v * v, red);
        float nrm = sqrtf(nsq);
        sXp[c][t] = v / fmaxf(nrm, 1e-12f);
    }
    __syncthreads();

    for (int c = 0; c < NC0; c++) {
        float s = 0.f;
        #pragma unroll
        for (int k = 0; k < NC0; k++) s += sA0[c * NC0 + k] * sXp[k][t];
        sM[c][t] = s;
    }
    __syncthreads();

    {
        float acc[NC0];
        #pragma unroll
        for (int c = 0; c < NC0; c++) acc[c] = me0_b[t];
        for (int k = 0; k < HID; k++) {
            float w = me0_w[k * HID + t];
            #pragma unroll
            for (int c = 0; c < NC0; c++) acc[c] += sM[c][k] * w;
        }
        #pragma unroll
        for (int c = 0; c < NC0; c++) {
            float v = tanhf(acc[c]);
            sL0[c][t] = v;
            g_latent0[c * HID + t] = v;
        }
    }
    __syncthreads();

    if (t < NC0 * NC1) {
        int k = t / NC1, c = t % NC1;
        float s = ml1_b[c] + gum1[k * NC1 + c];
        for (int j = 0; j < HID; j++) s += sL0[k][j] * ml1_w[j * NC1 + c];
        sZ[k][c] = s;
    }
    __syncthreads();
    if (t < NC0) {
        float best = sZ[t][0]; int bi = 0;
        #pragma unroll
        for (int c = 1; c < NC1; c++)
            if (sZ[t][c] > best) { best = sZ[t][c]; bi = c; }
        sC1[t] = bi;
        g_c1[t] = bi;
    }
    __syncthreads();

    for (int c = 0; c < NC1; c++) {
        float v = 0.f;
        #pragma unroll
        for (int k = 0; k < NC0; k++)
            if (sC1[k] == c) v += sL0[k][t];
        float nsq = blockReduce128(v * v, red);
        float nrm = sqrtf(nsq);
        sXp1[c][t] = v / fmaxf(nrm, 1e-12f);
    }
    __syncthreads();

    if (t < NC1 * NC1) {
        int aa = t / NC1, bb = t % NC1;
        float s = 0.f;
        for (int k = 0; k < NC0; k++)
            for (int l = 0; l < NC0; l++)
                if (sC1[k] == aa && sC1[l] == bb) s += sA0[k * NC0 + l];
        sA1[t] = s;
    }
    __syncthreads();
    float a1v = (t < NC1 * NC1) ? sA1[t] : 0.f;
    float S1 = blockReduce128(a1v, red);
    if (t < NC1 * NC1) sA1[t] = a1v / S1;
    __syncthreads();

    for (int c = 0; c < NC1; c++) {
        float s = 0.f;
        #pragma unroll
        for (int k = 0; k < NC1; k++) s += sA1[c * NC1 + k] * sXp1[k][t];
        sM1[c][t] = s;
    }
    __syncthreads();
    {
        float acc[NC1];
        #pragma unroll
        for (int c = 0; c < NC1; c++) acc[c] = me1_b[t];
        for (int k = 0; k < HID; k++) {
            float w = me1_w[k * HID + t];
            #pragma unroll
            for (int c = 0; c < NC1; c++) acc[c] += sM1[c][k] * w;
        }
        #pragma unroll
        for (int c = 0; c < NC1; c++) g_latent1[c * HID + t] = tanhf(acc[c]);
    }
}

// ---------------- final bias + relu ----------------
__global__ void k_fin(float* __restrict__ out, const float* __restrict__ b) {
    int i = blockIdx.x * blockDim.x + threadIdx.x;
    if (i < N_NODES) out[i] = fmaxf(out[i] + b[0], 0.f);
}

// ---------------- host ----------------
extern "C" void kernel_launch(void* const* d_in, const int* in_sizes, int n_in,
                              void* d_out, int out_size)
{
    const float* x       = (const float*)d_in[0];
    const float* ew      = (const float*)d_in[1];
    const float* gum0    = (const float*)d_in[2];
    const float* gum1    = (const float*)d_in[3];
    const float* conv1_w = (const float*)d_in[4];
    const float* conv1_b = (const float*)d_in[5];
    const float* conv2_w = (const float*)d_in[6];
    const float* conv2_b = (const float*)d_in[7];
    const float* bn1_g   = (const float*)d_in[8];
    const float* bn1_b   = (const float*)d_in[9];
    const float* bn2_g   = (const float*)d_in[10];
    const float* bn2_b   = (const float*)d_in[11];
    const float* enc1_w  = (const float*)d_in[12];
    const float* enc1_b  = (const float*)d_in[13];
    const float* enc2_w  = (const float*)d_in[14];
    const float* enc2_b  = (const float*)d_in[15];
    const float* ml0_w   = (const float*)d_in[16];
    const float* ml0_b   = (const float*)d_in[17];
    const float* ml1_w   = (const float*)d_in[18];
    const float* ml1_b   = (const float*)d_in[19];
    const float* me0_w   = (const float*)d_in[20];
    const float* me0_b   = (const float*)d_in[21];
    const float* me1_w   = (const float*)d_in[22];
    const float* me1_b   = (const float*)d_in[23];
    const float* fc1_w   = (const float*)d_in[24];
    const float* fc1_b   = (const float*)d_in[25];
    const float* fc2_w   = (const float*)d_in[26];
    const float* fc2_b   = (const float*)d_in[27];
    const int*   ei      = (const int*)d_in[28];
    const int* row = ei;
    const int* col = ei + N_EDGES;
    float* out = (float*)d_out;

    float *p_hlin, *p_pre1, *p_pre2, *p_e1, *p_bottom;
    float *p_stats1, *p_stats2, *p_lat0, *p_lat1;
    __nv_bfloat16 *p_wh, *p_wl;
    cudaGetSymbolAddress((void**)&p_hlin,   g_hlin);
    cudaGetSymbolAddress((void**)&p_pre1,   g_pre1);
    cudaGetSymbolAddress((void**)&p_pre2,   g_pre2);
    cudaGetSymbolAddress((void**)&p_e1,     g_e1);
    cudaGetSymbolAddress((void**)&p_bottom, g_bottom);
    cudaGetSymbolAddress((void**)&p_stats1, g_stats1);
    cudaGetSymbolAddress((void**)&p_stats2, g_stats2);
    cudaGetSymbolAddress((void**)&p_lat0,   g_latent0);
    cudaGetSymbolAddress((void**)&p_lat1,   g_latent1);
    cudaGetSymbolAddress((void**)&p_wh,     g_wh);
    cudaGetSymbolAddress((void**)&p_wl,     g_wl);

    const int GB = (N_NODES + 63) / 64;   // 157
    dim3 g2(GB, 2), g8(GB, 8);

    // side stream for edge infra, fork/join via events (capture-legal pattern)
    cudaStream_t side;
    cudaStreamCreateWithFlags(&side, cudaStreamNonBlocking);
    cudaEvent_t ev1, ev2;
    cudaEventCreateWithFlags(&ev1, cudaEventDisableTiming);
    cudaEventCreateWithFlags(&ev2, cudaEventDisableTiming);

    // #1 fused weight prep + zeroing (main)
    k_wz<<<(W_TOTAL + 255) / 256, 256>>>(conv1_w, conv2_w, enc1_w, enc2_w, fc1_w, out);
    cudaEventRecord(ev1, 0);
    cudaStreamWaitEvent(side, ev1, 0);
    // #2, #3 edge histogram + scan (side)
    k_count<<<(N_EDGES + 255) / 256, 256, 0, side>>>(col, ew);
    k_scan<<<1, 1024, 0, side>>>();
    // #4: conv1 GEMM (main, overlaps with edge infra)
    tgemm<<<g2, 256>>>(x, nullptr, nullptr,
                       nullptr, nullptr, nullptr, nullptr, nullptr, nullptr,
                       nullptr, nullptr, nullptr,
                       p_wh + WO_CONV1, p_wl + WO_CONV1, nullptr, p_hlin,
                       nullptr, nullptr, N_NODES, 1, 128, 0, 0);
    // #5 CSR fill (+ dinv) (side), then join
    k_fill<<<(N_EDGES + 255) / 256, 256, 0, side>>>(row, col, ew);
    cudaEventRecord(ev2, side);
    cudaStreamWaitEvent(0, ev2, 0);

    // conv1 aggregation
    k_gcn<<<1250, 256>>>(p_hlin, conv1_b, p_pre1, p_stats1);

    // conv2
    tgemm<<<g2, 256>>>(p_pre1, nullptr, nullptr,
                       p_stats1, bn1_g, bn1_b, nullptr, nullptr, nullptr,
                       nullptr, nullptr, nullptr,
                       p_wh + WO_CONV2, p_wl + WO_CONV2, nullptr, p_hlin,
                       nullptr, nullptr, N_NODES, 1, 128, 0, 0);
    k_gcn<<<1250, 256>>>(p_hlin, conv2_b, p_pre2, p_stats2);

    // enc1 / enc2
    tgemm<<<g2, 256>>>(x, p_pre1, p_pre2,
                       nullptr, nullptr, nullptr,
                       p_stats1, bn1_g, bn1_b,
                       p_stats2, bn2_g, bn2_b,
                       p_wh + WO_ENC1, p_wl + WO_ENC1, enc1_b, p_e1,
                       nullptr, nullptr, N_NODES, 3, 128, 1, 0);
    tgemm<<<g2, 256>>>(p_e1, nullptr, nullptr,
                       nullptr, nullptr, nullptr, nullptr, nullptr, nullptr,
                       nullptr, nullptr, nullptr,
                       p_wh + WO_ENC2, p_wl + WO_ENC2, enc2_b, p_bottom,
                       nullptr, nullptr, N_NODES, 1, 128, 1, 0);

    // hierarchical pooling
    k_assign0<<<80, 256>>>(ml0_w, ml0_b, gum0);
    k_A0<<<120, 256>>>(row, col, ew);
    k_levels<<<1, 128>>>(me0_w, me0_b, ml1_w, ml1_b, gum1, me1_w, me1_b);

    // fc1 with fused fc2 partial-dot epilogue
    tgemm<<<g8, 256>>>(p_bottom, p_lat0, p_lat1,
                       nullptr, nullptr, nullptr, nullptr, nullptr, nullptr,
                       nullptr, nullptr, nullptr,
                       p_wh + WO_FC1, p_wl + WO_FC1, fc1_b, nullptr,
                       fc2_w, out, N_NODES, 3, 512, 1, 1);
    k_fin<<<(N_NODES + 255) / 256, 256>>>(out, fc2_b);
}